// round 2
// baseline (speedup 1.0000x reference)
#include <cuda_runtime.h>

// MoE SwiGLU FFN, block-balanced (stk topology).
//  x  : [16384, 2048] f32
//  w1 : [8192, 2048]  f32   (per expert slice: [1024, 2048])
//  w2 : [8192, 2048]  f32
//  w3 : [8192, 2048]  f32
//  out: [16384, 2048] f32
//
// Kernel 1 (per expert e):  g = silu(x_e @ w1_e^T) * (x_e @ w2_e^T)   [2048 x 1024]
// Kernel 2 (per expert e):  out_e = g_e @ w3_e                        [2048 x 2048]

#define DD   2048   // model dim (K of gemm1/2, N of gemm3)
#define TT   16384  // tokens
#define EE   8      // experts
#define HE   1024   // hidden per expert
#define TE   2048   // tokens per expert

#define BM   128
#define BN1  64     // kernel1 N tile (per weight matrix)
#define BN3  128    // kernel3 N tile
#define BK   16

// Scratch for gated activations (graph-capturable: no runtime allocation).
__device__ float g_gate[(size_t)TT * HE];   // 64 MiB

__device__ __forceinline__ float silu_f(float v) {
    return v / (1.0f + __expf(-v));
}

// ---------------------------------------------------------------------------
// Kernel 1: fused sdd pair + SiLU gate.
// Block tile: 128 tokens x 64 hidden, both w1 and w2 in one pass (shared x tile).
// 256 threads, each computes 8x4 outputs for h1 AND h2.
// ---------------------------------------------------------------------------
__global__ __launch_bounds__(256, 2)
void moe_gemm12_kernel(const float* __restrict__ x,
                       const float* __restrict__ w1,
                       const float* __restrict__ w2)
{
    __shared__ float As [BK][132];  // transposed x tile, pad so rows stay 16B-aligned
    __shared__ float B1s[BK][68];   // transposed w1 tile
    __shared__ float B2s[BK][68];   // transposed w2 tile

    const int e   = blockIdx.z;
    const int m0  = blockIdx.y * BM;    // token offset within expert
    const int n0  = blockIdx.x * BN1;   // hidden offset within expert
    const int tid = threadIdx.x;
    const int tx  = tid & 15;           // n direction (16 threads * 4 = 64)
    const int ty  = tid >> 4;           // m direction (16 threads * 8 = 128)

    const float* Ag  = x  + ((size_t)e * TE + m0) * DD;
    const float* B1g = w1 + ((size_t)e * HE + n0) * DD;
    const float* B2g = w2 + ((size_t)e * HE + n0) * DD;

    // loader mapping: each thread owns float4 chunks of the k-slab
    const int arow0 = tid >> 2;           // 0..63
    const int arow1 = arow0 + 64;         // 64..127
    const int akq   = (tid & 3) << 2;     // 0,4,8,12
    const int brow  = tid >> 2;           // 0..63
    const int bkq   = akq;

    float4 ra0, ra1, rb1, rb2;

    // prologue: prefetch k-slab 0 into registers
    ra0 = *(const float4*)(Ag  + (size_t)arow0 * DD + akq);
    ra1 = *(const float4*)(Ag  + (size_t)arow1 * DD + akq);
    rb1 = *(const float4*)(B1g + (size_t)brow  * DD + bkq);
    rb2 = *(const float4*)(B2g + (size_t)brow  * DD + bkq);

    float acc1[8][4];
    float acc2[8][4];
    #pragma unroll
    for (int i = 0; i < 8; ++i)
        #pragma unroll
        for (int j = 0; j < 4; ++j) { acc1[i][j] = 0.0f; acc2[i][j] = 0.0f; }

    const int NT = DD / BK;  // 128 k-slabs
    for (int kt = 0; kt < NT; ++kt) {
        __syncthreads();  // previous compute done before overwriting smem

        // store prefetched registers into smem (transposed)
        As[akq + 0][arow0] = ra0.x; As[akq + 1][arow0] = ra0.y;
        As[akq + 2][arow0] = ra0.z; As[akq + 3][arow0] = ra0.w;
        As[akq + 0][arow1] = ra1.x; As[akq + 1][arow1] = ra1.y;
        As[akq + 2][arow1] = ra1.z; As[akq + 3][arow1] = ra1.w;
        B1s[bkq + 0][brow] = rb1.x; B1s[bkq + 1][brow] = rb1.y;
        B1s[bkq + 2][brow] = rb1.z; B1s[bkq + 3][brow] = rb1.w;
        B2s[bkq + 0][brow] = rb2.x; B2s[bkq + 1][brow] = rb2.y;
        B2s[bkq + 2][brow] = rb2.z; B2s[bkq + 3][brow] = rb2.w;

        __syncthreads();

        // prefetch next k-slab while computing this one
        if (kt + 1 < NT) {
            const int k0 = (kt + 1) * BK;
            ra0 = *(const float4*)(Ag  + (size_t)arow0 * DD + k0 + akq);
            ra1 = *(const float4*)(Ag  + (size_t)arow1 * DD + k0 + akq);
            rb1 = *(const float4*)(B1g + (size_t)brow  * DD + k0 + bkq);
            rb2 = *(const float4*)(B2g + (size_t)brow  * DD + k0 + bkq);
        }

        #pragma unroll
        for (int k = 0; k < BK; ++k) {
            float4 a0 = *(const float4*)&As[k][ty * 8];
            float4 a1 = *(const float4*)&As[k][ty * 8 + 4];
            float4 b1 = *(const float4*)&B1s[k][tx * 4];
            float4 b2 = *(const float4*)&B2s[k][tx * 4];
            float am[8] = {a0.x, a0.y, a0.z, a0.w, a1.x, a1.y, a1.z, a1.w};
            float v1[4] = {b1.x, b1.y, b1.z, b1.w};
            float v2[4] = {b2.x, b2.y, b2.z, b2.w};
            #pragma unroll
            for (int i = 0; i < 8; ++i) {
                #pragma unroll
                for (int j = 0; j < 4; ++j) {
                    acc1[i][j] = fmaf(am[i], v1[j], acc1[i][j]);
                    acc2[i][j] = fmaf(am[i], v2[j], acc2[i][j]);
                }
            }
        }
    }

    // epilogue: g = silu(h1) * h2, vectorized store
    const int t0 = e * TE + m0 + ty * 8;
    const int h0 = n0 + tx * 4;
    #pragma unroll
    for (int i = 0; i < 8; ++i) {
        float4 o;
        o.x = silu_f(acc1[i][0]) * acc2[i][0];
        o.y = silu_f(acc1[i][1]) * acc2[i][1];
        o.z = silu_f(acc1[i][2]) * acc2[i][2];
        o.w = silu_f(acc1[i][3]) * acc2[i][3];
        *(float4*)&g_gate[(size_t)(t0 + i) * HE + h0] = o;
    }
}

// ---------------------------------------------------------------------------
// Kernel 2: dsd  out_e = g_e @ w3_e   (A: [2048,1024] k-contig, B: [1024,2048] n-contig)
// Block tile 128x128, 256 threads, 8x8 per thread.
// ---------------------------------------------------------------------------
__global__ __launch_bounds__(256, 2)
void moe_gemm3_kernel(const float* __restrict__ w3,
                      float* __restrict__ out)
{
    __shared__ float As[BK][132];   // transposed g tile
    __shared__ float Bs[BK][BN3];   // natural-layout w3 tile

    const int e   = blockIdx.z;
    const int m0  = blockIdx.y * BM;
    const int n0  = blockIdx.x * BN3;
    const int tid = threadIdx.x;
    const int tx  = tid & 15;       // n (16 * (4+4 split) = 128)
    const int ty  = tid >> 4;       // m (16 * 8 = 128)

    const float* Ag = g_gate + ((size_t)e * TE + m0) * HE;
    const float* Bg = w3 + (size_t)e * HE * DD;

    const int arow0 = tid >> 2;
    const int arow1 = arow0 + 64;
    const int akq   = (tid & 3) << 2;
    const int brow0 = tid >> 5;           // 0..7
    const int brow1 = brow0 + 8;          // 8..15
    const int bcol  = (tid & 31) << 2;    // 0..124

    float4 ra0, ra1, rb0, rb1;

    ra0 = *(const float4*)(Ag + (size_t)arow0 * HE + akq);
    ra1 = *(const float4*)(Ag + (size_t)arow1 * HE + akq);
    rb0 = *(const float4*)(Bg + (size_t)brow0 * DD + n0 + bcol);
    rb1 = *(const float4*)(Bg + (size_t)brow1 * DD + n0 + bcol);

    float acc[8][8];
    #pragma unroll
    for (int i = 0; i < 8; ++i)
        #pragma unroll
        for (int j = 0; j < 8; ++j) acc[i][j] = 0.0f;

    const int NT = HE / BK;  // 64 k-slabs
    for (int kt = 0; kt < NT; ++kt) {
        __syncthreads();

        As[akq + 0][arow0] = ra0.x; As[akq + 1][arow0] = ra0.y;
        As[akq + 2][arow0] = ra0.z; As[akq + 3][arow0] = ra0.w;
        As[akq + 0][arow1] = ra1.x; As[akq + 1][arow1] = ra1.y;
        As[akq + 2][arow1] = ra1.z; As[akq + 3][arow1] = ra1.w;
        *(float4*)&Bs[brow0][bcol] = rb0;
        *(float4*)&Bs[brow1][bcol] = rb1;

        __syncthreads();

        if (kt + 1 < NT) {
            const int k0 = (kt + 1) * BK;
            ra0 = *(const float4*)(Ag + (size_t)arow0 * HE + k0 + akq);
            ra1 = *(const float4*)(Ag + (size_t)arow1 * HE + k0 + akq);
            rb0 = *(const float4*)(Bg + (size_t)(k0 + brow0) * DD + n0 + bcol);
            rb1 = *(const float4*)(Bg + (size_t)(k0 + brow1) * DD + n0 + bcol);
        }

        #pragma unroll
        for (int k = 0; k < BK; ++k) {
            float4 a0 = *(const float4*)&As[k][ty * 8];
            float4 a1 = *(const float4*)&As[k][ty * 8 + 4];
            float4 b0 = *(const float4*)&Bs[k][tx * 4];
            float4 b1 = *(const float4*)&Bs[k][64 + tx * 4];
            float am[8] = {a0.x, a0.y, a0.z, a0.w, a1.x, a1.y, a1.z, a1.w};
            float bn[8] = {b0.x, b0.y, b0.z, b0.w, b1.x, b1.y, b1.z, b1.w};
            #pragma unroll
            for (int i = 0; i < 8; ++i)
                #pragma unroll
                for (int j = 0; j < 8; ++j)
                    acc[i][j] = fmaf(am[i], bn[j], acc[i][j]);
        }
    }

    const int t0 = e * TE + m0 + ty * 8;
    const int d0 = n0 + tx * 4;
    #pragma unroll
    for (int i = 0; i < 8; ++i) {
        float4 o0, o1;
        o0.x = acc[i][0]; o0.y = acc[i][1]; o0.z = acc[i][2]; o0.w = acc[i][3];
        o1.x = acc[i][4]; o1.y = acc[i][5]; o1.z = acc[i][6]; o1.w = acc[i][7];
        *(float4*)&out[(size_t)(t0 + i) * DD + d0]      = o0;
        *(float4*)&out[(size_t)(t0 + i) * DD + d0 + 64] = o1;
    }
}

// ---------------------------------------------------------------------------
extern "C" void kernel_launch(void* const* d_in, const int* in_sizes, int n_in,
                              void* d_out, int out_size)
{
    const float* x  = (const float*)d_in[0];
    const float* w1 = (const float*)d_in[1];
    const float* w2 = (const float*)d_in[2];
    const float* w3 = (const float*)d_in[3];
    // d_in[4] = num_experts (8), baked into the tiling.
    float* out = (float*)d_out;

    dim3 g12(HE / BN1, TE / BM, EE);   // (16, 16, 8)
    moe_gemm12_kernel<<<g12, 256>>>(x, w1, w2);

    dim3 g3(DD / BN3, TE / BM, EE);    // (16, 16, 8)
    moe_gemm3_kernel<<<g3, 256>>>(w3, out);
}

// round 4
// speedup vs baseline: 2.1889x; 2.1889x over previous
#include <cuda_runtime.h>
#include <cuda_bf16.h>
#include <cstdint>

// MoE SwiGLU FFN via bf16 split-precision (hi/lo) mma.sync (base-target PTX:
// mma.sync.m16n8k16 + ldmatrix + cp.async — no 'a'-suffix instructions).
//  x  : [16384, 2048] f32,  w1/w2/w3 : [8192, 2048] f32,  out : [16384, 2048] f32
//  GEMM12: h1 = x_e @ w1_e^T, h2 = x_e @ w2_e^T, g = silu(h1)*h2  (dual-acc, fused)
//  GEMM3 : out_e = g_e @ w3_e  (w3 pre-transposed to [e][d][h] so K is contiguous)

#define DD 2048
#define TT 16384
#define EE 8
#define HE 1024
#define TE 2048

// ---------------- static device scratch ----------------
__device__ __nv_bfloat16 g_xhi [(size_t)TT * DD];
__device__ __nv_bfloat16 g_xlo [(size_t)TT * DD];
__device__ __nv_bfloat16 g_w1hi[(size_t)EE * HE * DD];
__device__ __nv_bfloat16 g_w1lo[(size_t)EE * HE * DD];
__device__ __nv_bfloat16 g_w2hi[(size_t)EE * HE * DD];
__device__ __nv_bfloat16 g_w2lo[(size_t)EE * HE * DD];
__device__ __nv_bfloat16 g_w3thi[(size_t)EE * DD * HE];   // [e][d][h]
__device__ __nv_bfloat16 g_w3tlo[(size_t)EE * DD * HE];
__device__ __nv_bfloat16 g_ghi [(size_t)TT * HE];
__device__ __nv_bfloat16 g_glo [(size_t)TT * HE];

// ---------------- base-target PTX helpers ----------------
__device__ __forceinline__ uint32_t smem_u32(const void* p) {
    return (uint32_t)__cvta_generic_to_shared(p);
}
__device__ __forceinline__ void cp16(uint32_t dst, const void* src) {
    asm volatile("cp.async.cg.shared.global [%0], [%1], 16;" :: "r"(dst), "l"(src));
}
__device__ __forceinline__ void cp_commit() {
    asm volatile("cp.async.commit_group;" ::: "memory");
}
__device__ __forceinline__ void cp_wait2() {
    asm volatile("cp.async.wait_group 2;" ::: "memory");
}
__device__ __forceinline__ void ldsm4(uint32_t* r, uint32_t addr) {
    asm volatile("ldmatrix.sync.aligned.m8n8.x4.shared.b16 {%0,%1,%2,%3}, [%4];"
                 : "=r"(r[0]), "=r"(r[1]), "=r"(r[2]), "=r"(r[3]) : "r"(addr));
}
__device__ __forceinline__ void mma16816(float* c, const uint32_t* a,
                                         uint32_t b0, uint32_t b1) {
    asm volatile(
        "mma.sync.aligned.m16n8k16.row.col.f32.bf16.bf16.f32 "
        "{%0,%1,%2,%3}, {%4,%5,%6,%7}, {%8,%9}, {%0,%1,%2,%3};"
        : "+f"(c[0]), "+f"(c[1]), "+f"(c[2]), "+f"(c[3])
        : "r"(a[0]), "r"(a[1]), "r"(a[2]), "r"(a[3]), "r"(b0), "r"(b1));
}
__device__ __forceinline__ uint32_t pack_bf16x2(__nv_bfloat16 a, __nv_bfloat16 b) {
    return (uint32_t)__bfloat16_as_ushort(a) | ((uint32_t)__bfloat16_as_ushort(b) << 16);
}

// Tile format: 128 rows x 32 bf16 cols (64B/row, 8KB). 16B chunks with
// XOR swizzle phys_c = c ^ ((row>>1)&3): conflict-free for cp.async stores
// and for every 8-address ldmatrix phase.
#define TILE_BYTES 8192

// cp.async load of one tile: 512 chunks, NT threads do 512/NT each.
template <int LDE, int NT>
__device__ __forceinline__ void load_tile(const __nv_bfloat16* __restrict__ src,
                                          uint32_t dst_base, int k0, int tid) {
    #pragma unroll
    for (int j = 0; j < 512 / NT; ++j) {
        int q = tid + NT * j;
        int r = q >> 2, c = q & 3;
        uint32_t dst = dst_base + r * 64 + ((c ^ ((r >> 1) & 3)) << 4);
        cp16(dst, src + (size_t)r * LDE + k0 + c * 8);
    }
}

// ---------------------------------------------------------------------------
// preprocessing: fp32 -> bf16 hi/lo split
// ---------------------------------------------------------------------------
__global__ void split_kernel(const float* __restrict__ in,
                             __nv_bfloat16* __restrict__ hi,
                             __nv_bfloat16* __restrict__ lo, int n4) {
    int idx = blockIdx.x * blockDim.x + threadIdx.x;
    int stride = gridDim.x * blockDim.x;
    for (int i = idx; i < n4; i += stride) {
        float4 v = ((const float4*)in)[i];
        __nv_bfloat16 h0 = __float2bfloat16(v.x), h1 = __float2bfloat16(v.y);
        __nv_bfloat16 h2 = __float2bfloat16(v.z), h3 = __float2bfloat16(v.w);
        __nv_bfloat16 l0 = __float2bfloat16(v.x - __bfloat162float(h0));
        __nv_bfloat16 l1 = __float2bfloat16(v.y - __bfloat162float(h1));
        __nv_bfloat16 l2 = __float2bfloat16(v.z - __bfloat162float(h2));
        __nv_bfloat16 l3 = __float2bfloat16(v.w - __bfloat162float(h3));
        ((uint2*)hi)[i] = make_uint2(pack_bf16x2(h0, h1), pack_bf16x2(h2, h3));
        ((uint2*)lo)[i] = make_uint2(pack_bf16x2(l0, l1), pack_bf16x2(l2, l3));
    }
}

// w3 [e][h][d] -> w3t [e][d][h], split hi/lo
__global__ void w3_transpose_split(const float* __restrict__ w3,
                                   __nv_bfloat16* __restrict__ hi,
                                   __nv_bfloat16* __restrict__ lo) {
    __shared__ float ts[32][33];
    const int e = blockIdx.z;
    const int h0 = blockIdx.x * 32, d0 = blockIdx.y * 32;
    const int tx = threadIdx.x, ty = threadIdx.y;  // 32 x 8
    const float* src = w3 + (size_t)e * HE * DD;
    #pragma unroll
    for (int r = 0; r < 32; r += 8)
        ts[ty + r][tx] = src[(size_t)(h0 + ty + r) * DD + d0 + tx];
    __syncthreads();
    __nv_bfloat16* dh = hi + (size_t)e * DD * HE;
    __nv_bfloat16* dl = lo + (size_t)e * DD * HE;
    #pragma unroll
    for (int r = 0; r < 32; r += 8) {
        float v = ts[tx][ty + r];
        __nv_bfloat16 h = __float2bfloat16(v);
        dh[(size_t)(d0 + ty + r) * HE + h0 + tx] = h;
        dl[(size_t)(d0 + ty + r) * HE + h0 + tx] =
            __float2bfloat16(v - __bfloat162float(h));
    }
}

// ---------------------------------------------------------------------------
// GEMM12: CTA = 128 tokens x 128 hidden, dual accumulators for w1/w2.
// 8 warps (2 m x 4 n), warp tile 64x32. K staged 32 wide, 3-stage cp.async.
// smem: 3 stages x 6 tiles x 8KB = 144KB dynamic.
// ---------------------------------------------------------------------------
#define ST12 (6 * TILE_BYTES)   // 48KB per stage

__global__ void __launch_bounds__(256, 1) moe_mma12() {
    extern __shared__ __align__(128) char smem[];
    const uint32_t sb = smem_u32(smem);

    const int tid = threadIdx.x;
    const int wid = tid >> 5, lane = tid & 31;
    const int warp_m = wid >> 2, warp_n = wid & 3;
    const int e = blockIdx.z;
    const int m0 = blockIdx.y * 128;
    const int n0 = blockIdx.x * 128;

    const __nv_bfloat16* sXH = g_xhi  + (size_t)(e * TE + m0) * DD;
    const __nv_bfloat16* sXL = g_xlo  + (size_t)(e * TE + m0) * DD;
    const __nv_bfloat16* sW1H = g_w1hi + (size_t)(e * HE + n0) * DD;
    const __nv_bfloat16* sW1L = g_w1lo + (size_t)(e * HE + n0) * DD;
    const __nv_bfloat16* sW2H = g_w2hi + (size_t)(e * HE + n0) * DD;
    const __nv_bfloat16* sW2L = g_w2lo + (size_t)(e * HE + n0) * DD;

    // per-thread ldmatrix address components
    uint32_t aRow[4], aS[4];          // A: 4 m16 tiles
    #pragma unroll
    for (int mi = 0; mi < 4; ++mi) {
        int r = warp_m * 64 + mi * 16 + (lane & 15);
        aRow[mi] = r * 64;
        aS[mi] = (r >> 1) & 3;
    }
    const uint32_t aC = lane >> 4;
    uint32_t bRow[2], bS[2];          // B: 2 groups of 16 n-rows
    #pragma unroll
    for (int gj = 0; gj < 2; ++gj) {
        int r = warp_n * 32 + gj * 16 + (lane & 7) + ((lane & 16) >> 1);
        bRow[gj] = r * 64;
        bS[gj] = (r >> 1) & 3;
    }
    const uint32_t bC = (lane >> 3) & 1;

    float acc1[4][4][4], acc2[4][4][4];
    #pragma unroll
    for (int mi = 0; mi < 4; ++mi)
        #pragma unroll
        for (int ni = 0; ni < 4; ++ni)
            #pragma unroll
            for (int q = 0; q < 4; ++q) { acc1[mi][ni][q] = 0.f; acc2[mi][ni][q] = 0.f; }

    auto load_stage = [&](int st, int buf) {
        const int k0 = st * 32;
        const uint32_t b = sb + buf * ST12;
        load_tile<DD, 256>(sXH,  b,                  k0, tid);
        load_tile<DD, 256>(sXL,  b + TILE_BYTES,     k0, tid);
        load_tile<DD, 256>(sW1H, b + 2 * TILE_BYTES, k0, tid);
        load_tile<DD, 256>(sW1L, b + 3 * TILE_BYTES, k0, tid);
        load_tile<DD, 256>(sW2H, b + 4 * TILE_BYTES, k0, tid);
        load_tile<DD, 256>(sW2L, b + 5 * TILE_BYTES, k0, tid);
    };

    const int NC = DD / 32;   // 64 stages
    load_stage(0, 0); cp_commit();
    load_stage(1, 1); cp_commit();

    for (int i = 0; i < NC; ++i) {
        if (i + 2 < NC) load_stage(i + 2, (i + 2) % 3);
        cp_commit();
        cp_wait2();
        __syncthreads();

        const uint32_t tXH = sb + (i % 3) * ST12;
        const uint32_t tXL = tXH + TILE_BYTES;
        const uint32_t tW1H = tXH + 2 * TILE_BYTES;
        const uint32_t tW1L = tXH + 3 * TILE_BYTES;
        const uint32_t tW2H = tXH + 4 * TILE_BYTES;
        const uint32_t tW2L = tXH + 5 * TILE_BYTES;

        #pragma unroll
        for (int step = 0; step < 2; ++step) {
            const uint32_t kc = step * 2;
            uint32_t Ah[4][4], Al[4][4];
            #pragma unroll
            for (int mi = 0; mi < 4; ++mi) {
                uint32_t co = (((kc + aC) ^ aS[mi]) << 4);
                ldsm4(Ah[mi], tXH + aRow[mi] + co);
                ldsm4(Al[mi], tXL + aRow[mi] + co);
            }
            uint32_t Bh[2][4], Bl[2][4];
            // ---- w1 passes -> acc1 ----
            #pragma unroll
            for (int gj = 0; gj < 2; ++gj) {
                uint32_t co = (((kc + bC) ^ bS[gj]) << 4);
                ldsm4(Bh[gj], tW1H + bRow[gj] + co);
                ldsm4(Bl[gj], tW1L + bRow[gj] + co);
            }
            #pragma unroll
            for (int mi = 0; mi < 4; ++mi)
                #pragma unroll
                for (int ni = 0; ni < 4; ++ni) {
                    const int gj = ni >> 1, p = (ni & 1) * 2;
                    mma16816(acc1[mi][ni], Ah[mi], Bh[gj][p], Bh[gj][p + 1]);
                    mma16816(acc1[mi][ni], Ah[mi], Bl[gj][p], Bl[gj][p + 1]);
                    mma16816(acc1[mi][ni], Al[mi], Bh[gj][p], Bh[gj][p + 1]);
                }
            // ---- w2 passes -> acc2 ----
            #pragma unroll
            for (int gj = 0; gj < 2; ++gj) {
                uint32_t co = (((kc + bC) ^ bS[gj]) << 4);
                ldsm4(Bh[gj], tW2H + bRow[gj] + co);
                ldsm4(Bl[gj], tW2L + bRow[gj] + co);
            }
            #pragma unroll
            for (int mi = 0; mi < 4; ++mi)
                #pragma unroll
                for (int ni = 0; ni < 4; ++ni) {
                    const int gj = ni >> 1, p = (ni & 1) * 2;
                    mma16816(acc2[mi][ni], Ah[mi], Bh[gj][p], Bh[gj][p + 1]);
                    mma16816(acc2[mi][ni], Ah[mi], Bl[gj][p], Bl[gj][p + 1]);
                    mma16816(acc2[mi][ni], Al[mi], Bh[gj][p], Bh[gj][p + 1]);
                }
        }
        __syncthreads();
    }

    // epilogue: g = silu(h1)*h2, split bf16 hi/lo, store
    const int row_base = e * TE + m0 + warp_m * 64;
    const int col_base = n0 + warp_n * 32;
    #pragma unroll
    for (int mi = 0; mi < 4; ++mi)
        #pragma unroll
        for (int ni = 0; ni < 4; ++ni) {
            const int r0 = row_base + mi * 16 + (lane >> 2);
            const int col = col_base + ni * 8 + 2 * (lane & 3);
            #pragma unroll
            for (int h = 0; h < 2; ++h) {   // h=0: rows r0, h=1: r0+8
                const float h1a = acc1[mi][ni][2 * h],     h1b = acc1[mi][ni][2 * h + 1];
                const float h2a = acc2[mi][ni][2 * h],     h2b = acc2[mi][ni][2 * h + 1];
                const float ga = h1a / (1.0f + __expf(-h1a)) * h2a;
                const float gb = h1b / (1.0f + __expf(-h1b)) * h2b;
                __nv_bfloat16 ha = __float2bfloat16(ga), hb = __float2bfloat16(gb);
                __nv_bfloat16 la = __float2bfloat16(ga - __bfloat162float(ha));
                __nv_bfloat16 lb = __float2bfloat16(gb - __bfloat162float(hb));
                const size_t off = (size_t)(r0 + 8 * h) * HE + col;
                *(uint32_t*)(g_ghi + off) = pack_bf16x2(ha, hb);
                *(uint32_t*)(g_glo + off) = pack_bf16x2(la, lb);
            }
        }
}

// ---------------------------------------------------------------------------
// GEMM3: out_e = g_e @ w3_e. CTA 128 tokens x 128 dims, K=1024 staged 32 wide.
// smem: 3 stages x 4 tiles x 8KB = 96KB.
// ---------------------------------------------------------------------------
#define ST3 (4 * TILE_BYTES)    // 32KB per stage

__global__ void __launch_bounds__(256, 1) moe_mma3(float* __restrict__ out) {
    extern __shared__ __align__(128) char smem[];
    const uint32_t sb = smem_u32(smem);

    const int tid = threadIdx.x;
    const int wid = tid >> 5, lane = tid & 31;
    const int warp_m = wid >> 2, warp_n = wid & 3;
    const int e = blockIdx.z;
    const int m0 = blockIdx.y * 128;
    const int n0 = blockIdx.x * 128;

    const __nv_bfloat16* sAH = g_ghi + (size_t)(e * TE + m0) * HE;
    const __nv_bfloat16* sAL = g_glo + (size_t)(e * TE + m0) * HE;
    const __nv_bfloat16* sBH = g_w3thi + (size_t)e * DD * HE + (size_t)n0 * HE;
    const __nv_bfloat16* sBL = g_w3tlo + (size_t)e * DD * HE + (size_t)n0 * HE;

    uint32_t aRow[4], aS[4];
    #pragma unroll
    for (int mi = 0; mi < 4; ++mi) {
        int r = warp_m * 64 + mi * 16 + (lane & 15);
        aRow[mi] = r * 64;
        aS[mi] = (r >> 1) & 3;
    }
    const uint32_t aC = lane >> 4;
    uint32_t bRow[2], bS[2];
    #pragma unroll
    for (int gj = 0; gj < 2; ++gj) {
        int r = warp_n * 32 + gj * 16 + (lane & 7) + ((lane & 16) >> 1);
        bRow[gj] = r * 64;
        bS[gj] = (r >> 1) & 3;
    }
    const uint32_t bC = (lane >> 3) & 1;

    float acc[4][4][4];
    #pragma unroll
    for (int mi = 0; mi < 4; ++mi)
        #pragma unroll
        for (int ni = 0; ni < 4; ++ni)
            #pragma unroll
            for (int q = 0; q < 4; ++q) acc[mi][ni][q] = 0.f;

    auto load_stage = [&](int st, int buf) {
        const int k0 = st * 32;
        const uint32_t b = sb + buf * ST3;
        load_tile<HE, 256>(sAH, b,                  k0, tid);
        load_tile<HE, 256>(sAL, b + TILE_BYTES,     k0, tid);
        load_tile<HE, 256>(sBH, b + 2 * TILE_BYTES, k0, tid);
        load_tile<HE, 256>(sBL, b + 3 * TILE_BYTES, k0, tid);
    };

    const int NC = HE / 32;   // 32 stages
    load_stage(0, 0); cp_commit();
    load_stage(1, 1); cp_commit();

    for (int i = 0; i < NC; ++i) {
        if (i + 2 < NC) load_stage(i + 2, (i + 2) % 3);
        cp_commit();
        cp_wait2();
        __syncthreads();

        const uint32_t tAH = sb + (i % 3) * ST3;
        const uint32_t tAL = tAH + TILE_BYTES;
        const uint32_t tBH = tAH + 2 * TILE_BYTES;
        const uint32_t tBL = tAH + 3 * TILE_BYTES;

        #pragma unroll
        for (int step = 0; step < 2; ++step) {
            const uint32_t kc = step * 2;
            uint32_t Ah[4][4], Al[4][4], Bh[2][4], Bl[2][4];
            #pragma unroll
            for (int mi = 0; mi < 4; ++mi) {
                uint32_t co = (((kc + aC) ^ aS[mi]) << 4);
                ldsm4(Ah[mi], tAH + aRow[mi] + co);
                ldsm4(Al[mi], tAL + aRow[mi] + co);
            }
            #pragma unroll
            for (int gj = 0; gj < 2; ++gj) {
                uint32_t co = (((kc + bC) ^ bS[gj]) << 4);
                ldsm4(Bh[gj], tBH + bRow[gj] + co);
                ldsm4(Bl[gj], tBL + bRow[gj] + co);
            }
            #pragma unroll
            for (int mi = 0; mi < 4; ++mi)
                #pragma unroll
                for (int ni = 0; ni < 4; ++ni) {
                    const int gj = ni >> 1, p = (ni & 1) * 2;
                    mma16816(acc[mi][ni], Ah[mi], Bh[gj][p], Bh[gj][p + 1]);
                    mma16816(acc[mi][ni], Ah[mi], Bl[gj][p], Bl[gj][p + 1]);
                    mma16816(acc[mi][ni], Al[mi], Bh[gj][p], Bh[gj][p + 1]);
                }
        }
        __syncthreads();
    }

    const int row_base = e * TE + m0 + warp_m * 64;
    const int col_base = n0 + warp_n * 32;
    #pragma unroll
    for (int mi = 0; mi < 4; ++mi)
        #pragma unroll
        for (int ni = 0; ni < 4; ++ni) {
            const int r0 = row_base + mi * 16 + (lane >> 2);
            const int col = col_base + ni * 8 + 2 * (lane & 3);
            *(float2*)(out + (size_t)r0 * DD + col) =
                make_float2(acc[mi][ni][0], acc[mi][ni][1]);
            *(float2*)(out + (size_t)(r0 + 8) * DD + col) =
                make_float2(acc[mi][ni][2], acc[mi][ni][3]);
        }
}

// ---------------------------------------------------------------------------
extern "C" void kernel_launch(void* const* d_in, const int* in_sizes, int n_in,
                              void* d_out, int out_size)
{
    const float* x  = (const float*)d_in[0];
    const float* w1 = (const float*)d_in[1];
    const float* w2 = (const float*)d_in[2];
    const float* w3 = (const float*)d_in[3];
    float* out = (float*)d_out;

    static bool attr_done = false;
    if (!attr_done) {
        cudaFuncSetAttribute(moe_mma12, cudaFuncAttributeMaxDynamicSharedMemorySize, 3 * ST12);
        cudaFuncSetAttribute(moe_mma3,  cudaFuncAttributeMaxDynamicSharedMemorySize, 3 * ST3);
        attr_done = true;
    }

    __nv_bfloat16 *xhi, *xlo, *w1hi, *w1lo, *w2hi, *w2lo, *w3thi, *w3tlo;
    cudaGetSymbolAddress((void**)&xhi,  g_xhi);
    cudaGetSymbolAddress((void**)&xlo,  g_xlo);
    cudaGetSymbolAddress((void**)&w1hi, g_w1hi);
    cudaGetSymbolAddress((void**)&w1lo, g_w1lo);
    cudaGetSymbolAddress((void**)&w2hi, g_w2hi);
    cudaGetSymbolAddress((void**)&w2lo, g_w2lo);
    cudaGetSymbolAddress((void**)&w3thi, g_w3thi);
    cudaGetSymbolAddress((void**)&w3tlo, g_w3tlo);

    split_kernel<<<2048, 256>>>(x,  xhi,  xlo,  (int)((size_t)TT * DD / 4));
    split_kernel<<<2048, 256>>>(w1, w1hi, w1lo, (int)((size_t)EE * HE * DD / 4));
    split_kernel<<<2048, 256>>>(w2, w2hi, w2lo, (int)((size_t)EE * HE * DD / 4));
    {
        dim3 tb(32, 8);
        dim3 tg(HE / 32, DD / 32, EE);
        w3_transpose_split<<<tg, tb>>>(w3, w3thi, w3tlo);
    }
    {
        dim3 g12(HE / 128, TE / 128, EE);   // 1024 CTAs
        moe_mma12<<<g12, 256, 3 * ST12>>>();
    }
    {
        dim3 g3(DD / 128, TE / 128, EE);    // 2048 CTAs
        moe_mma3<<<g3, 256, 3 * ST3>>>(out);
    }
}

// round 5
// speedup vs baseline: 5.1072x; 2.3332x over previous
#include <cuda_runtime.h>
#include <cuda_fp16.h>
#include <cstdint>

// MoE SwiGLU FFN via single-pass fp16 mma.sync.m16n8k16 (base-target PTX).
//  x  : [16384, 2048] f32,  w1/w2/w3 : [8192, 2048] f32,  out : [16384, 2048] f32
//  GEMM12: h1 = x_e @ w1_e^T, h2 = x_e @ w2_e^T, g = silu(h1)*h2  (dual-acc fused)
//  GEMM3 : out_e = g_e @ w3_e  (w3 pre-transposed to [e][d][h], K contiguous)

#define DD 2048
#define TT 16384
#define EE 8
#define HE 1024
#define TE 2048

// ---------------- static device scratch ----------------
__device__ __half g_xh [(size_t)TT * DD];
__device__ __half g_w1h[(size_t)EE * HE * DD];
__device__ __half g_w2h[(size_t)EE * HE * DD];
__device__ __half g_w3t[(size_t)EE * DD * HE];   // [e][d][h]
__device__ __half g_g  [(size_t)TT * HE];

// ---------------- base-target PTX helpers ----------------
__device__ __forceinline__ uint32_t smem_u32(const void* p) {
    return (uint32_t)__cvta_generic_to_shared(p);
}
__device__ __forceinline__ void cp16(uint32_t dst, const void* src) {
    asm volatile("cp.async.cg.shared.global [%0], [%1], 16;" :: "r"(dst), "l"(src));
}
__device__ __forceinline__ void cp_commit() {
    asm volatile("cp.async.commit_group;" ::: "memory");
}
__device__ __forceinline__ void cp_wait3() {
    asm volatile("cp.async.wait_group 3;" ::: "memory");
}
__device__ __forceinline__ void ldsm4(uint32_t* r, uint32_t addr) {
    asm volatile("ldmatrix.sync.aligned.m8n8.x4.shared.b16 {%0,%1,%2,%3}, [%4];"
                 : "=r"(r[0]), "=r"(r[1]), "=r"(r[2]), "=r"(r[3]) : "r"(addr));
}
__device__ __forceinline__ void mma16816(float* c, const uint32_t* a,
                                         uint32_t b0, uint32_t b1) {
    asm volatile(
        "mma.sync.aligned.m16n8k16.row.col.f32.f16.f16.f32 "
        "{%0,%1,%2,%3}, {%4,%5,%6,%7}, {%8,%9}, {%0,%1,%2,%3};"
        : "+f"(c[0]), "+f"(c[1]), "+f"(c[2]), "+f"(c[3])
        : "r"(a[0]), "r"(a[1]), "r"(a[2]), "r"(a[3]), "r"(b0), "r"(b1));
}
__device__ __forceinline__ uint32_t pack_h2(__half a, __half b) {
    return (uint32_t)__half_as_ushort(a) | ((uint32_t)__half_as_ushort(b) << 16);
}

// Tile: 128 rows x 32 fp16 cols (64B/row, 8KB). 16B chunks, XOR swizzle
// phys_c = c ^ ((row>>1)&3) — conflict-free for cp.async stores & ldmatrix.
#define TILE_BYTES 8192

template <int LDE>
__device__ __forceinline__ void load_tile(const __half* __restrict__ src,
                                          uint32_t dst_base, int k0, int tid) {
    #pragma unroll
    for (int j = 0; j < 2; ++j) {                // 512 chunks / 256 threads
        int q = tid + 256 * j;
        int r = q >> 2, c = q & 3;
        uint32_t dst = dst_base + r * 64 + ((c ^ ((r >> 1) & 3)) << 4);
        cp16(dst, src + (size_t)r * LDE + k0 + c * 8);
    }
}

// ---------------------------------------------------------------------------
// preprocessing: fp32 -> fp16 (8 elems/thread)
// ---------------------------------------------------------------------------
__global__ void to_half_kernel(const float* __restrict__ in,
                               __half* __restrict__ dst, int n8) {
    int idx = blockIdx.x * blockDim.x + threadIdx.x;
    int stride = gridDim.x * blockDim.x;
    for (int i = idx; i < n8; i += stride) {
        float4 v0 = ((const float4*)in)[2 * i];
        float4 v1 = ((const float4*)in)[2 * i + 1];
        uint4 o;
        o.x = pack_h2(__float2half_rn(v0.x), __float2half_rn(v0.y));
        o.y = pack_h2(__float2half_rn(v0.z), __float2half_rn(v0.w));
        o.z = pack_h2(__float2half_rn(v1.x), __float2half_rn(v1.y));
        o.w = pack_h2(__float2half_rn(v1.z), __float2half_rn(v1.w));
        ((uint4*)dst)[i] = o;
    }
}

// w3 [e][h][d] -> w3t [e][d][h] fp16
__global__ void w3_transpose_half(const float* __restrict__ w3,
                                  __half* __restrict__ dst) {
    __shared__ float ts[32][33];
    const int e = blockIdx.z;
    const int h0 = blockIdx.x * 32, d0 = blockIdx.y * 32;
    const int tx = threadIdx.x, ty = threadIdx.y;  // 32 x 8
    const float* src = w3 + (size_t)e * HE * DD;
    #pragma unroll
    for (int r = 0; r < 32; r += 8)
        ts[ty + r][tx] = src[(size_t)(h0 + ty + r) * DD + d0 + tx];
    __syncthreads();
    __half* dh = dst + (size_t)e * DD * HE;
    #pragma unroll
    for (int r = 0; r < 32; r += 8)
        dh[(size_t)(d0 + ty + r) * HE + h0 + tx] = __float2half_rn(ts[tx][ty + r]);
}

// ---------------------------------------------------------------------------
// GEMM12: CTA = 128 tokens x 128 hidden, dual accumulators (w1/w2 share A).
// 8 warps (2m x 4n), warp tile 64x32. K staged 32 wide, 4-stage cp.async.
// smem: 4 stages x 3 tiles x 8KB = 96KB dynamic.
// ---------------------------------------------------------------------------
#define ST12 (3 * TILE_BYTES)

__global__ void __launch_bounds__(256, 1) moe_mma12() {
    extern __shared__ __align__(128) char smem[];
    const uint32_t sb = smem_u32(smem);

    const int tid = threadIdx.x;
    const int wid = tid >> 5, lane = tid & 31;
    const int warp_m = wid >> 2, warp_n = wid & 3;
    const int e = blockIdx.z;
    const int m0 = blockIdx.y * 128;
    const int n0 = blockIdx.x * 128;

    const __half* sX  = g_xh  + (size_t)(e * TE + m0) * DD;
    const __half* sW1 = g_w1h + (size_t)(e * HE + n0) * DD;
    const __half* sW2 = g_w2h + (size_t)(e * HE + n0) * DD;

    uint32_t aRow[4], aS[4];
    #pragma unroll
    for (int mi = 0; mi < 4; ++mi) {
        int r = warp_m * 64 + mi * 16 + (lane & 15);
        aRow[mi] = r * 64;
        aS[mi] = (r >> 1) & 3;
    }
    const uint32_t aC = lane >> 4;
    uint32_t bRow[2], bS[2];
    #pragma unroll
    for (int gj = 0; gj < 2; ++gj) {
        int r = warp_n * 32 + gj * 16 + (lane & 7) + ((lane & 16) >> 1);
        bRow[gj] = r * 64;
        bS[gj] = (r >> 1) & 3;
    }
    const uint32_t bC = (lane >> 3) & 1;

    float acc1[4][4][4], acc2[4][4][4];
    #pragma unroll
    for (int mi = 0; mi < 4; ++mi)
        #pragma unroll
        for (int ni = 0; ni < 4; ++ni)
            #pragma unroll
            for (int q = 0; q < 4; ++q) { acc1[mi][ni][q] = 0.f; acc2[mi][ni][q] = 0.f; }

    auto load_stage = [&](int st, int buf) {
        const int k0 = st * 32;
        const uint32_t b = sb + buf * ST12;
        load_tile<DD>(sX,  b,                  k0, tid);
        load_tile<DD>(sW1, b + TILE_BYTES,     k0, tid);
        load_tile<DD>(sW2, b + 2 * TILE_BYTES, k0, tid);
    };

    const int NC = DD / 32;   // 64 stages
    load_stage(0, 0); cp_commit();
    load_stage(1, 1); cp_commit();
    load_stage(2, 2); cp_commit();

    for (int i = 0; i < NC; ++i) {
        if (i + 3 < NC) load_stage(i + 3, (i + 3) & 3);
        cp_commit();
        cp_wait3();
        __syncthreads();

        const uint32_t tX  = sb + (i & 3) * ST12;
        const uint32_t tW1 = tX + TILE_BYTES;
        const uint32_t tW2 = tX + 2 * TILE_BYTES;

        #pragma unroll
        for (int step = 0; step < 2; ++step) {
            const uint32_t kc = step * 2;
            uint32_t A[4][4], B1[2][4], B2[2][4];
            #pragma unroll
            for (int mi = 0; mi < 4; ++mi)
                ldsm4(A[mi], tX + aRow[mi] + (((kc + aC) ^ aS[mi]) << 4));
            #pragma unroll
            for (int gj = 0; gj < 2; ++gj) {
                uint32_t co = (((kc + bC) ^ bS[gj]) << 4);
                ldsm4(B1[gj], tW1 + bRow[gj] + co);
                ldsm4(B2[gj], tW2 + bRow[gj] + co);
            }
            #pragma unroll
            for (int mi = 0; mi < 4; ++mi)
                #pragma unroll
                for (int ni = 0; ni < 4; ++ni) {
                    const int gj = ni >> 1, p = (ni & 1) * 2;
                    mma16816(acc1[mi][ni], A[mi], B1[gj][p], B1[gj][p + 1]);
                    mma16816(acc2[mi][ni], A[mi], B2[gj][p], B2[gj][p + 1]);
                }
        }
        __syncthreads();
    }

    // epilogue: g = silu(h1)*h2 -> fp16
    const int row_base = e * TE + m0 + warp_m * 64;
    const int col_base = n0 + warp_n * 32;
    #pragma unroll
    for (int mi = 0; mi < 4; ++mi)
        #pragma unroll
        for (int ni = 0; ni < 4; ++ni) {
            const int r0 = row_base + mi * 16 + (lane >> 2);
            const int col = col_base + ni * 8 + 2 * (lane & 3);
            #pragma unroll
            for (int h = 0; h < 2; ++h) {
                const float h1a = acc1[mi][ni][2 * h], h1b = acc1[mi][ni][2 * h + 1];
                const float h2a = acc2[mi][ni][2 * h], h2b = acc2[mi][ni][2 * h + 1];
                const float ga = h1a / (1.0f + __expf(-h1a)) * h2a;
                const float gb = h1b / (1.0f + __expf(-h1b)) * h2b;
                *(uint32_t*)(g_g + (size_t)(r0 + 8 * h) * HE + col) =
                    pack_h2(__float2half_rn(ga), __float2half_rn(gb));
            }
        }
}

// ---------------------------------------------------------------------------
// GEMM3: out_e = g_e @ w3_e. CTA 128x128, K=1024 staged 32 wide, 4 stages.
// smem: 4 x 2 x 8KB = 64KB -> 2 CTAs/SM.
// ---------------------------------------------------------------------------
#define ST3 (2 * TILE_BYTES)

__global__ void __launch_bounds__(256, 2) moe_mma3(float* __restrict__ out) {
    extern __shared__ __align__(128) char smem[];
    const uint32_t sb = smem_u32(smem);

    const int tid = threadIdx.x;
    const int wid = tid >> 5, lane = tid & 31;
    const int warp_m = wid >> 2, warp_n = wid & 3;
    const int e = blockIdx.z;
    const int m0 = blockIdx.y * 128;
    const int n0 = blockIdx.x * 128;

    const __half* sA = g_g   + (size_t)(e * TE + m0) * HE;
    const __half* sB = g_w3t + (size_t)e * DD * HE + (size_t)n0 * HE;

    uint32_t aRow[4], aS[4];
    #pragma unroll
    for (int mi = 0; mi < 4; ++mi) {
        int r = warp_m * 64 + mi * 16 + (lane & 15);
        aRow[mi] = r * 64;
        aS[mi] = (r >> 1) & 3;
    }
    const uint32_t aC = lane >> 4;
    uint32_t bRow[2], bS[2];
    #pragma unroll
    for (int gj = 0; gj < 2; ++gj) {
        int r = warp_n * 32 + gj * 16 + (lane & 7) + ((lane & 16) >> 1);
        bRow[gj] = r * 64;
        bS[gj] = (r >> 1) & 3;
    }
    const uint32_t bC = (lane >> 3) & 1;

    float acc[4][4][4];
    #pragma unroll
    for (int mi = 0; mi < 4; ++mi)
        #pragma unroll
        for (int ni = 0; ni < 4; ++ni)
            #pragma unroll
            for (int q = 0; q < 4; ++q) acc[mi][ni][q] = 0.f;

    auto load_stage = [&](int st, int buf) {
        const int k0 = st * 32;
        const uint32_t b = sb + buf * ST3;
        load_tile<HE>(sA, b,              k0, tid);
        load_tile<HE>(sB, b + TILE_BYTES, k0, tid);
    };

    const int NC = HE / 32;   // 32 stages
    load_stage(0, 0); cp_commit();
    load_stage(1, 1); cp_commit();
    load_stage(2, 2); cp_commit();

    for (int i = 0; i < NC; ++i) {
        if (i + 3 < NC) load_stage(i + 3, (i + 3) & 3);
        cp_commit();
        cp_wait3();
        __syncthreads();

        const uint32_t tA = sb + (i & 3) * ST3;
        const uint32_t tB = tA + TILE_BYTES;

        #pragma unroll
        for (int step = 0; step < 2; ++step) {
            const uint32_t kc = step * 2;
            uint32_t A[4][4], B[2][4];
            #pragma unroll
            for (int mi = 0; mi < 4; ++mi)
                ldsm4(A[mi], tA + aRow[mi] + (((kc + aC) ^ aS[mi]) << 4));
            #pragma unroll
            for (int gj = 0; gj < 2; ++gj)
                ldsm4(B[gj], tB + bRow[gj] + (((kc + bC) ^ bS[gj]) << 4));
            #pragma unroll
            for (int mi = 0; mi < 4; ++mi)
                #pragma unroll
                for (int ni = 0; ni < 4; ++ni) {
                    const int gj = ni >> 1, p = (ni & 1) * 2;
                    mma16816(acc[mi][ni], A[mi], B[gj][p], B[gj][p + 1]);
                }
        }
        __syncthreads();
    }

    const int row_base = e * TE + m0 + warp_m * 64;
    const int col_base = n0 + warp_n * 32;
    #pragma unroll
    for (int mi = 0; mi < 4; ++mi)
        #pragma unroll
        for (int ni = 0; ni < 4; ++ni) {
            const int r0 = row_base + mi * 16 + (lane >> 2);
            const int col = col_base + ni * 8 + 2 * (lane & 3);
            *(float2*)(out + (size_t)r0 * DD + col) =
                make_float2(acc[mi][ni][0], acc[mi][ni][1]);
            *(float2*)(out + (size_t)(r0 + 8) * DD + col) =
                make_float2(acc[mi][ni][2], acc[mi][ni][3]);
        }
}

// ---------------------------------------------------------------------------
extern "C" void kernel_launch(void* const* d_in, const int* in_sizes, int n_in,
                              void* d_out, int out_size)
{
    const float* x  = (const float*)d_in[0];
    const float* w1 = (const float*)d_in[1];
    const float* w2 = (const float*)d_in[2];
    const float* w3 = (const float*)d_in[3];
    float* out = (float*)d_out;

    static bool attr_done = false;
    if (!attr_done) {
        cudaFuncSetAttribute(moe_mma12, cudaFuncAttributeMaxDynamicSharedMemorySize, 4 * ST12);
        cudaFuncSetAttribute(moe_mma3,  cudaFuncAttributeMaxDynamicSharedMemorySize, 4 * ST3);
        attr_done = true;
    }

    __half *xh, *w1h, *w2h, *w3t;
    cudaGetSymbolAddress((void**)&xh,  g_xh);
    cudaGetSymbolAddress((void**)&w1h, g_w1h);
    cudaGetSymbolAddress((void**)&w2h, g_w2h);
    cudaGetSymbolAddress((void**)&w3t, g_w3t);

    to_half_kernel<<<2048, 256>>>(x,  xh,  (int)((size_t)TT * DD / 8));
    to_half_kernel<<<2048, 256>>>(w1, w1h, (int)((size_t)EE * HE * DD / 8));
    to_half_kernel<<<2048, 256>>>(w2, w2h, (int)((size_t)EE * HE * DD / 8));
    {
        dim3 tb(32, 8);
        dim3 tg(HE / 32, DD / 32, EE);
        w3_transpose_half<<<tg, tb>>>(w3, w3t);
    }
    {
        dim3 g12(HE / 128, TE / 128, EE);   // 1024 CTAs
        moe_mma12<<<g12, 256, 4 * ST12>>>();
    }
    {
        dim3 g3(DD / 128, TE / 128, EE);    // 2048 CTAs
        moe_mma3<<<g3, 256, 4 * ST3>>>(out);
    }
}

// round 8
// speedup vs baseline: 5.6287x; 1.1021x over previous
#include <cuda_runtime.h>
#include <cuda_fp16.h>
#include <cstdint>

// MoE SwiGLU FFN via single-pass fp16 mma.sync.m16n8k16 (base-target PTX).
//  x  : [16384, 2048] f32,  w1/w2/w3 : [8192, 2048] f32,  out : [16384, 2048] f32
//  GEMM12: h1 = x_e @ w1_e^T, h2 = x_e @ w2_e^T, g = silu(h1)*h2  (dual-acc fused)
//  GEMM3 : out_e = g_e @ w3_e  (w3 pre-transposed to [e][d][h], K contiguous)

#define DD 2048
#define TT 16384
#define EE 8
#define HE 1024
#define TE 2048

// ---------------- static device scratch ----------------
__device__ __half g_xh [(size_t)TT * DD];
__device__ __half g_w1h[(size_t)EE * HE * DD];
__device__ __half g_w2h[(size_t)EE * HE * DD];
__device__ __half g_w3t[(size_t)EE * DD * HE];   // [e][d][h]
__device__ __half g_g  [(size_t)TT * HE];

// ---------------- base-target PTX helpers ----------------
__device__ __forceinline__ uint32_t smem_u32(const void* p) {
    return (uint32_t)__cvta_generic_to_shared(p);
}
__device__ __forceinline__ void cp16(uint32_t dst, const void* src) {
    asm volatile("cp.async.cg.shared.global [%0], [%1], 16;" :: "r"(dst), "l"(src));
}
__device__ __forceinline__ void cp_commit() {
    asm volatile("cp.async.commit_group;" ::: "memory");
}
template <int N>
__device__ __forceinline__ void cp_wait() {
    asm volatile("cp.async.wait_group %0;" :: "n"(N) : "memory");
}
__device__ __forceinline__ void ldsm4(uint32_t* r, uint32_t addr) {
    asm volatile("ldmatrix.sync.aligned.m8n8.x4.shared.b16 {%0,%1,%2,%3}, [%4];"
                 : "=r"(r[0]), "=r"(r[1]), "=r"(r[2]), "=r"(r[3]) : "r"(addr));
}
__device__ __forceinline__ void mma16816(float* c, const uint32_t* a,
                                         uint32_t b0, uint32_t b1) {
    asm volatile(
        "mma.sync.aligned.m16n8k16.row.col.f32.f16.f16.f32 "
        "{%0,%1,%2,%3}, {%4,%5,%6,%7}, {%8,%9}, {%0,%1,%2,%3};"
        : "+f"(c[0]), "+f"(c[1]), "+f"(c[2]), "+f"(c[3])
        : "r"(a[0]), "r"(a[1]), "r"(a[2]), "r"(a[3]), "r"(b0), "r"(b1));
}
__device__ __forceinline__ uint32_t pack_h2(__half a, __half b) {
    return (uint32_t)__half_as_ushort(a) | ((uint32_t)__half_as_ushort(b) << 16);
}

// ---------------------------------------------------------------------------
// preprocessing: fp32 -> fp16 (8 elems/thread)
// ---------------------------------------------------------------------------
__global__ void to_half_kernel(const float* __restrict__ in,
                               __half* __restrict__ dst, int n8) {
    int idx = blockIdx.x * blockDim.x + threadIdx.x;
    int stride = gridDim.x * blockDim.x;
    for (int i = idx; i < n8; i += stride) {
        float4 v0 = ((const float4*)in)[2 * i];
        float4 v1 = ((const float4*)in)[2 * i + 1];
        uint4 o;
        o.x = pack_h2(__float2half_rn(v0.x), __float2half_rn(v0.y));
        o.y = pack_h2(__float2half_rn(v0.z), __float2half_rn(v0.w));
        o.z = pack_h2(__float2half_rn(v1.x), __float2half_rn(v1.y));
        o.w = pack_h2(__float2half_rn(v1.z), __float2half_rn(v1.w));
        ((uint4*)dst)[i] = o;
    }
}

// w3 [e][h][d] -> w3t [e][d][h] fp16
__global__ void w3_transpose_half(const float* __restrict__ w3,
                                  __half* __restrict__ dst) {
    __shared__ float ts[32][33];
    const int e = blockIdx.z;
    const int h0 = blockIdx.x * 32, d0 = blockIdx.y * 32;
    const int tx = threadIdx.x, ty = threadIdx.y;  // 32 x 8
    const float* src = w3 + (size_t)e * HE * DD;
    #pragma unroll
    for (int r = 0; r < 32; r += 8)
        ts[ty + r][tx] = src[(size_t)(h0 + ty + r) * DD + d0 + tx];
    __syncthreads();
    __half* dh = dst + (size_t)e * DD * HE;
    #pragma unroll
    for (int r = 0; r < 32; r += 8)
        dh[(size_t)(d0 + ty + r) * HE + h0 + tx] = __float2half_rn(ts[tx][ty + r]);
}

// ---------------------------------------------------------------------------
// GEMM12: CTA = 128 tokens x 128 hidden, dual accumulators (w1/w2 share A).
// 8 warps (2m x 4n), warp tile 64x32 per weight. K staged 64 wide (16KB tiles,
// 128B rows, swizzle c ^= r&7), 3-buffer cp.async pipeline.
// Pattern per iter (proven in R5): load i+2 -> (i+2)%3, commit, wait<2>,
// sync (stage i visible to ALL threads), compute stage i, sync (readers done
// before the next iteration overwrites this buffer).
// smem: 3 x 3 x 16KB = 144KB.
// ---------------------------------------------------------------------------
#define TB12 16384          // tile bytes (128 rows x 128B)
#define ST12 (3 * TB12)     // stage bytes

// 16KB tile load: 1024 16B-chunks, 256 threads x 4.
template <int LDE>
__device__ __forceinline__ void load_tile64(const __half* __restrict__ src,
                                            uint32_t dst_base, int k0, int tid) {
    #pragma unroll
    for (int j = 0; j < 4; ++j) {
        int q = tid + 256 * j;
        int r = q >> 3, c = q & 7;
        uint32_t dst = dst_base + r * 128 + ((c ^ (r & 7)) << 4);
        cp16(dst, src + (size_t)r * LDE + k0 + c * 8);
    }
}

__global__ void __launch_bounds__(256, 1) moe_mma12() {
    extern __shared__ __align__(128) char smem[];
    const uint32_t sb = smem_u32(smem);

    const int tid = threadIdx.x;
    const int wid = tid >> 5, lane = tid & 31;
    const int warp_m = wid >> 2, warp_n = wid & 3;
    const int e = blockIdx.z;
    const int m0 = blockIdx.y * 128;
    const int n0 = blockIdx.x * 128;

    const __half* sX  = g_xh  + (size_t)(e * TE + m0) * DD;
    const __half* sW1 = g_w1h + (size_t)(e * HE + n0) * DD;
    const __half* sW2 = g_w2h + (size_t)(e * HE + n0) * DD;

    uint32_t aRow[4], aS[4];
    #pragma unroll
    for (int mi = 0; mi < 4; ++mi) {
        int r = warp_m * 64 + mi * 16 + (lane & 15);
        aRow[mi] = r * 128;
        aS[mi] = r & 7;
    }
    const uint32_t aC = lane >> 4;
    uint32_t bRow[2], bS[2];
    #pragma unroll
    for (int gj = 0; gj < 2; ++gj) {
        int r = warp_n * 32 + gj * 16 + (lane & 7) + ((lane & 16) >> 1);
        bRow[gj] = r * 128;
        bS[gj] = r & 7;
    }
    const uint32_t bC = (lane >> 3) & 1;

    float acc1[4][4][4], acc2[4][4][4];
    #pragma unroll
    for (int mi = 0; mi < 4; ++mi)
        #pragma unroll
        for (int ni = 0; ni < 4; ++ni)
            #pragma unroll
            for (int q = 0; q < 4; ++q) { acc1[mi][ni][q] = 0.f; acc2[mi][ni][q] = 0.f; }

    auto load_stage = [&](int st, int buf) {
        const int k0 = st * 64;
        const uint32_t b = sb + buf * ST12;
        load_tile64<DD>(sX,  b,            k0, tid);
        load_tile64<DD>(sW1, b + TB12,     k0, tid);
        load_tile64<DD>(sW2, b + 2 * TB12, k0, tid);
    };

    const int NC = DD / 64;   // 32 stages
    load_stage(0, 0); cp_commit();
    load_stage(1, 1); cp_commit();

    for (int i = 0; i < NC; ++i) {
        // load stage i+2 into buffer (i+2)%3 == (i-1)%3; its readers finished
        // at iter i-1, ordered by that iteration's trailing __syncthreads.
        if (i + 2 < NC) load_stage(i + 2, (i + 2) % 3);
        cp_commit();
        cp_wait<2>();          // this thread's groups up to stage i complete
        __syncthreads();       // ALL threads' stage-i copies now visible

        const uint32_t tX  = sb + (i % 3) * ST12;
        const uint32_t tW1 = tX + TB12;
        const uint32_t tW2 = tX + 2 * TB12;

        #pragma unroll
        for (int ks = 0; ks < 4; ++ks) {        // 4 k16 steps per stage
            const uint32_t kc = ks * 2;
            uint32_t A[4][4], B1[2][4], B2[2][4];
            #pragma unroll
            for (int mi = 0; mi < 4; ++mi)
                ldsm4(A[mi], tX + aRow[mi] + (((kc + aC) ^ aS[mi]) << 4));
            #pragma unroll
            for (int gj = 0; gj < 2; ++gj) {
                uint32_t c1 = (((kc + bC) ^ bS[gj]) << 4);
                ldsm4(B1[gj], tW1 + bRow[gj] + c1);
                ldsm4(B2[gj], tW2 + bRow[gj] + c1);
            }
            #pragma unroll
            for (int mi = 0; mi < 4; ++mi)
                #pragma unroll
                for (int ni = 0; ni < 4; ++ni) {
                    const int gj = ni >> 1, p = (ni & 1) * 2;
                    mma16816(acc1[mi][ni], A[mi], B1[gj][p], B1[gj][p + 1]);
                    mma16816(acc2[mi][ni], A[mi], B2[gj][p], B2[gj][p + 1]);
                }
        }
        __syncthreads();       // readers done before next iter overwrites
    }

    // epilogue: g = silu(h1)*h2 -> fp16
    const int row_base = e * TE + m0 + warp_m * 64;
    const int col_base = n0 + warp_n * 32;
    #pragma unroll
    for (int mi = 0; mi < 4; ++mi)
        #pragma unroll
        for (int ni = 0; ni < 4; ++ni) {
            const int r0 = row_base + mi * 16 + (lane >> 2);
            const int col = col_base + ni * 8 + 2 * (lane & 3);
            #pragma unroll
            for (int h = 0; h < 2; ++h) {
                const float h1a = acc1[mi][ni][2 * h], h1b = acc1[mi][ni][2 * h + 1];
                const float h2a = acc2[mi][ni][2 * h], h2b = acc2[mi][ni][2 * h + 1];
                const float ga = h1a / (1.0f + __expf(-h1a)) * h2a;
                const float gb = h1b / (1.0f + __expf(-h1b)) * h2b;
                *(uint32_t*)(g_g + (size_t)(r0 + 8 * h) * HE + col) =
                    pack_h2(__float2half_rn(ga), __float2half_rn(gb));
            }
        }
}

// ---------------------------------------------------------------------------
// GEMM3 (verbatim from the passing R5 version): out_e = g_e @ w3_e.
// CTA 128x128, K=1024 staged 32 wide (8KB tiles, 64B rows, swizzle
// c ^ ((r>>1)&3)), 4 stages, 2 CTA/SM. smem: 4 x 2 x 8KB = 64KB.
// ---------------------------------------------------------------------------
#define TB3 8192
#define ST3 (2 * TB3)

template <int LDE>
__device__ __forceinline__ void load_tile32(const __half* __restrict__ src,
                                            uint32_t dst_base, int k0, int tid) {
    #pragma unroll
    for (int j = 0; j < 2; ++j) {
        int q = tid + 256 * j;
        int r = q >> 2, c = q & 3;
        uint32_t dst = dst_base + r * 64 + ((c ^ ((r >> 1) & 3)) << 4);
        cp16(dst, src + (size_t)r * LDE + k0 + c * 8);
    }
}

__global__ void __launch_bounds__(256, 2) moe_mma3(float* __restrict__ out) {
    extern __shared__ __align__(128) char smem[];
    const uint32_t sb = smem_u32(smem);

    const int tid = threadIdx.x;
    const int wid = tid >> 5, lane = tid & 31;
    const int warp_m = wid >> 2, warp_n = wid & 3;
    const int e = blockIdx.z;
    const int m0 = blockIdx.y * 128;
    const int n0 = blockIdx.x * 128;

    const __half* sA = g_g   + (size_t)(e * TE + m0) * HE;
    const __half* sB = g_w3t + (size_t)e * DD * HE + (size_t)n0 * HE;

    uint32_t aRow[4], aS[4];
    #pragma unroll
    for (int mi = 0; mi < 4; ++mi) {
        int r = warp_m * 64 + mi * 16 + (lane & 15);
        aRow[mi] = r * 64;
        aS[mi] = (r >> 1) & 3;
    }
    const uint32_t aC = lane >> 4;
    uint32_t bRow[2], bS[2];
    #pragma unroll
    for (int gj = 0; gj < 2; ++gj) {
        int r = warp_n * 32 + gj * 16 + (lane & 7) + ((lane & 16) >> 1);
        bRow[gj] = r * 64;
        bS[gj] = (r >> 1) & 3;
    }
    const uint32_t bC = (lane >> 3) & 1;

    float acc[4][4][4];
    #pragma unroll
    for (int mi = 0; mi < 4; ++mi)
        #pragma unroll
        for (int ni = 0; ni < 4; ++ni)
            #pragma unroll
            for (int q = 0; q < 4; ++q) acc[mi][ni][q] = 0.f;

    auto load_stage = [&](int st, int buf) {
        const int k0 = st * 32;
        const uint32_t b = sb + buf * ST3;
        load_tile32<HE>(sA, b,       k0, tid);
        load_tile32<HE>(sB, b + TB3, k0, tid);
    };

    const int NC = HE / 32;   // 32 stages
    load_stage(0, 0); cp_commit();
    load_stage(1, 1); cp_commit();
    load_stage(2, 2); cp_commit();

    for (int i = 0; i < NC; ++i) {
        if (i + 3 < NC) load_stage(i + 3, (i + 3) & 3);
        cp_commit();
        cp_wait<3>();
        __syncthreads();

        const uint32_t tA = sb + (i & 3) * ST3;
        const uint32_t tB = tA + TB3;

        #pragma unroll
        for (int ks = 0; ks < 2; ++ks) {
            const uint32_t kc = ks * 2;
            uint32_t A[4][4], B[2][4];
            #pragma unroll
            for (int mi = 0; mi < 4; ++mi)
                ldsm4(A[mi], tA + aRow[mi] + (((kc + aC) ^ aS[mi]) << 4));
            #pragma unroll
            for (int gj = 0; gj < 2; ++gj)
                ldsm4(B[gj], tB + bRow[gj] + (((kc + bC) ^ bS[gj]) << 4));
            #pragma unroll
            for (int mi = 0; mi < 4; ++mi)
                #pragma unroll
                for (int ni = 0; ni < 4; ++ni) {
                    const int gj = ni >> 1, p = (ni & 1) * 2;
                    mma16816(acc[mi][ni], A[mi], B[gj][p], B[gj][p + 1]);
                }
        }
        __syncthreads();
    }

    const int row_base = e * TE + m0 + warp_m * 64;
    const int col_base = n0 + warp_n * 32;
    #pragma unroll
    for (int mi = 0; mi < 4; ++mi)
        #pragma unroll
        for (int ni = 0; ni < 4; ++ni) {
            const int r0 = row_base + mi * 16 + (lane >> 2);
            const int col = col_base + ni * 8 + 2 * (lane & 3);
            *(float2*)(out + (size_t)r0 * DD + col) =
                make_float2(acc[mi][ni][0], acc[mi][ni][1]);
            *(float2*)(out + (size_t)(r0 + 8) * DD + col) =
                make_float2(acc[mi][ni][2], acc[mi][ni][3]);
        }
}

// ---------------------------------------------------------------------------
extern "C" void kernel_launch(void* const* d_in, const int* in_sizes, int n_in,
                              void* d_out, int out_size)
{
    const float* x  = (const float*)d_in[0];
    const float* w1 = (const float*)d_in[1];
    const float* w2 = (const float*)d_in[2];
    const float* w3 = (const float*)d_in[3];
    float* out = (float*)d_out;

    cudaFuncSetAttribute(moe_mma12, cudaFuncAttributeMaxDynamicSharedMemorySize, 3 * ST12);
    cudaFuncSetAttribute(moe_mma3,  cudaFuncAttributeMaxDynamicSharedMemorySize, 4 * ST3);

    __half *xh, *w1h, *w2h, *w3t;
    cudaGetSymbolAddress((void**)&xh,  g_xh);
    cudaGetSymbolAddress((void**)&w1h, g_w1h);
    cudaGetSymbolAddress((void**)&w2h, g_w2h);
    cudaGetSymbolAddress((void**)&w3t, g_w3t);

    to_half_kernel<<<2048, 256>>>(x,  xh,  (int)((size_t)TT * DD / 8));
    to_half_kernel<<<2048, 256>>>(w1, w1h, (int)((size_t)EE * HE * DD / 8));
    to_half_kernel<<<2048, 256>>>(w2, w2h, (int)((size_t)EE * HE * DD / 8));
    {
        dim3 tb(32, 8);
        dim3 tg(HE / 32, DD / 32, EE);
        w3_transpose_half<<<tg, tb>>>(w3, w3t);
    }
    {
        dim3 g12(HE / 128, TE / 128, EE);   // 1024 CTAs
        moe_mma12<<<g12, 256, 3 * ST12>>>();
    }
    {
        dim3 g3(DD / 128, TE / 128, EE);    // 2048 CTAs
        moe_mma3<<<g3, 256, 4 * ST3>>>(out);
    }
}

// round 9
// speedup vs baseline: 5.8197x; 1.0339x over previous
#include <cuda_runtime.h>
#include <cuda_fp16.h>
#include <cstdint>

// MoE SwiGLU FFN via single-pass fp16 mma.sync.m16n8k16 (base-target PTX).
//  x  : [16384, 2048] f32,  w1/w2/w3 : [8192, 2048] f32,  out : [16384, 2048] f32
//  GEMM12: h1 = x_e @ w1_e^T, h2 = x_e @ w2_e^T, g = silu(h1)*h2  (dual-acc fused)
//  GEMM3 : out_e = g_e @ w3_e  (w3 pre-transposed to [e][d][h], K contiguous)

#define DD 2048
#define TT 16384
#define EE 8
#define HE 1024
#define TE 2048

// ---------------- static device scratch ----------------
__device__ __half g_xh [(size_t)TT * DD];
__device__ __half g_w1h[(size_t)EE * HE * DD];
__device__ __half g_w2h[(size_t)EE * HE * DD];
__device__ __half g_w3t[(size_t)EE * DD * HE];   // [e][d][h]
__device__ __half g_g  [(size_t)TT * HE];

// ---------------- base-target PTX helpers ----------------
__device__ __forceinline__ uint32_t smem_u32(const void* p) {
    return (uint32_t)__cvta_generic_to_shared(p);
}
__device__ __forceinline__ void cp16(uint32_t dst, const void* src) {
    asm volatile("cp.async.cg.shared.global [%0], [%1], 16;" :: "r"(dst), "l"(src));
}
__device__ __forceinline__ void cp_commit() {
    asm volatile("cp.async.commit_group;" ::: "memory");
}
template <int N>
__device__ __forceinline__ void cp_wait() {
    asm volatile("cp.async.wait_group %0;" :: "n"(N) : "memory");
}
__device__ __forceinline__ void ldsm4(uint32_t* r, uint32_t addr) {
    asm volatile("ldmatrix.sync.aligned.m8n8.x4.shared.b16 {%0,%1,%2,%3}, [%4];"
                 : "=r"(r[0]), "=r"(r[1]), "=r"(r[2]), "=r"(r[3]) : "r"(addr));
}
__device__ __forceinline__ void mma16816(float* c, const uint32_t* a,
                                         uint32_t b0, uint32_t b1) {
    asm volatile(
        "mma.sync.aligned.m16n8k16.row.col.f32.f16.f16.f32 "
        "{%0,%1,%2,%3}, {%4,%5,%6,%7}, {%8,%9}, {%0,%1,%2,%3};"
        : "+f"(c[0]), "+f"(c[1]), "+f"(c[2]), "+f"(c[3])
        : "r"(a[0]), "r"(a[1]), "r"(a[2]), "r"(a[3]), "r"(b0), "r"(b1));
}
__device__ __forceinline__ uint32_t pack_h2(__half a, __half b) {
    return (uint32_t)__half_as_ushort(a) | ((uint32_t)__half_as_ushort(b) << 16);
}

// ---------------------------------------------------------------------------
// preprocessing: one kernel converts x, w1, w2 fp32 -> fp16 (8 elems/iter).
// ---------------------------------------------------------------------------
#define N8X  ((int)((size_t)TT * DD / 8))           // 4.19M
#define N8W  ((int)((size_t)EE * HE * DD / 8))      // 2.10M

__global__ void convert_all_kernel(const float* __restrict__ x,
                                   const float* __restrict__ w1,
                                   const float* __restrict__ w2,
                                   __half* __restrict__ xh,
                                   __half* __restrict__ w1h,
                                   __half* __restrict__ w2h) {
    const int total = N8X + 2 * N8W;
    int idx = blockIdx.x * blockDim.x + threadIdx.x;
    int stride = gridDim.x * blockDim.x;
    for (int i = idx; i < total; i += stride) {
        const float* in;
        __half* dst;
        int j = i;
        if (j < N8X)            { in = x;  dst = xh; }
        else if (j < N8X + N8W) { in = w1; dst = w1h; j -= N8X; }
        else                    { in = w2; dst = w2h; j -= N8X + N8W; }
        float4 v0 = ((const float4*)in)[2 * j];
        float4 v1 = ((const float4*)in)[2 * j + 1];
        uint4 o;
        o.x = pack_h2(__float2half_rn(v0.x), __float2half_rn(v0.y));
        o.y = pack_h2(__float2half_rn(v0.z), __float2half_rn(v0.w));
        o.z = pack_h2(__float2half_rn(v1.x), __float2half_rn(v1.y));
        o.w = pack_h2(__float2half_rn(v1.z), __float2half_rn(v1.w));
        ((uint4*)dst)[j] = o;
    }
}

// w3 [e][h][d] -> w3t [e][d][h] fp16
__global__ void w3_transpose_half(const float* __restrict__ w3,
                                  __half* __restrict__ dst) {
    __shared__ float ts[32][33];
    const int e = blockIdx.z;
    const int h0 = blockIdx.x * 32, d0 = blockIdx.y * 32;
    const int tx = threadIdx.x, ty = threadIdx.y;  // 32 x 8
    const float* src = w3 + (size_t)e * HE * DD;
    #pragma unroll
    for (int r = 0; r < 32; r += 8)
        ts[ty + r][tx] = src[(size_t)(h0 + ty + r) * DD + d0 + tx];
    __syncthreads();
    __half* dh = dst + (size_t)e * DD * HE;
    #pragma unroll
    for (int r = 0; r < 32; r += 8)
        dh[(size_t)(d0 + ty + r) * HE + h0 + tx] = __float2half_rn(ts[tx][ty + r]);
}

// ---------------------------------------------------------------------------
// Shared tile machinery: 128 rows x 64 fp16 cols (128B rows, 16KB),
// swizzle c ^= r&7 — conflict-free for cp.async stores & all ldmatrix phases.
// ---------------------------------------------------------------------------
#define TBL 16384

template <int LDE>
__device__ __forceinline__ void load_tile64(const __half* __restrict__ src,
                                            uint32_t dst_base, int k0, int tid) {
    #pragma unroll
    for (int j = 0; j < 4; ++j) {
        int q = tid + 256 * j;
        int r = q >> 3, c = q & 7;
        uint32_t dst = dst_base + r * 128 + ((c ^ (r & 7)) << 4);
        cp16(dst, src + (size_t)r * LDE + k0 + c * 8);
    }
}

// ---------------------------------------------------------------------------
// GEMM12: CTA = 128 tokens x 128 hidden, dual accumulators (w1/w2 share A).
// 8 warps (2m x 4n), warp tile 64x32 per weight. K staged 64 wide, 3 buffers.
// Proven pattern: load i+2 -> (i+2)%3, commit, wait<2>, sync, compute, sync.
// smem: 3 x 3 x 16KB = 144KB.
// ---------------------------------------------------------------------------
#define ST12 (3 * TBL)

__global__ void __launch_bounds__(256, 1) moe_mma12() {
    extern __shared__ __align__(128) char smem[];
    const uint32_t sb = smem_u32(smem);

    const int tid = threadIdx.x;
    const int wid = tid >> 5, lane = tid & 31;
    const int warp_m = wid >> 2, warp_n = wid & 3;
    const int e = blockIdx.z;
    const int m0 = blockIdx.y * 128;
    const int n0 = blockIdx.x * 128;

    const __half* sX  = g_xh  + (size_t)(e * TE + m0) * DD;
    const __half* sW1 = g_w1h + (size_t)(e * HE + n0) * DD;
    const __half* sW2 = g_w2h + (size_t)(e * HE + n0) * DD;

    uint32_t aRow[4], aS[4];
    #pragma unroll
    for (int mi = 0; mi < 4; ++mi) {
        int r = warp_m * 64 + mi * 16 + (lane & 15);
        aRow[mi] = r * 128;
        aS[mi] = r & 7;
    }
    const uint32_t aC = lane >> 4;
    uint32_t bRow[2], bS[2];
    #pragma unroll
    for (int gj = 0; gj < 2; ++gj) {
        int r = warp_n * 32 + gj * 16 + (lane & 7) + ((lane & 16) >> 1);
        bRow[gj] = r * 128;
        bS[gj] = r & 7;
    }
    const uint32_t bC = (lane >> 3) & 1;

    float acc1[4][4][4], acc2[4][4][4];
    #pragma unroll
    for (int mi = 0; mi < 4; ++mi)
        #pragma unroll
        for (int ni = 0; ni < 4; ++ni)
            #pragma unroll
            for (int q = 0; q < 4; ++q) { acc1[mi][ni][q] = 0.f; acc2[mi][ni][q] = 0.f; }

    auto load_stage = [&](int st, int buf) {
        const int k0 = st * 64;
        const uint32_t b = sb + buf * ST12;
        load_tile64<DD>(sX,  b,           k0, tid);
        load_tile64<DD>(sW1, b + TBL,     k0, tid);
        load_tile64<DD>(sW2, b + 2 * TBL, k0, tid);
    };

    const int NC = DD / 64;   // 32 stages
    load_stage(0, 0); cp_commit();
    load_stage(1, 1); cp_commit();

    for (int i = 0; i < NC; ++i) {
        if (i + 2 < NC) load_stage(i + 2, (i + 2) % 3);
        cp_commit();
        cp_wait<2>();
        __syncthreads();

        const uint32_t tX  = sb + (i % 3) * ST12;
        const uint32_t tW1 = tX + TBL;
        const uint32_t tW2 = tX + 2 * TBL;

        #pragma unroll
        for (int ks = 0; ks < 4; ++ks) {
            const uint32_t kc = ks * 2;
            uint32_t A[4][4], B1[2][4], B2[2][4];
            #pragma unroll
            for (int mi = 0; mi < 4; ++mi)
                ldsm4(A[mi], tX + aRow[mi] + (((kc + aC) ^ aS[mi]) << 4));
            #pragma unroll
            for (int gj = 0; gj < 2; ++gj) {
                uint32_t c1 = (((kc + bC) ^ bS[gj]) << 4);
                ldsm4(B1[gj], tW1 + bRow[gj] + c1);
                ldsm4(B2[gj], tW2 + bRow[gj] + c1);
            }
            #pragma unroll
            for (int mi = 0; mi < 4; ++mi)
                #pragma unroll
                for (int ni = 0; ni < 4; ++ni) {
                    const int gj = ni >> 1, p = (ni & 1) * 2;
                    mma16816(acc1[mi][ni], A[mi], B1[gj][p], B1[gj][p + 1]);
                    mma16816(acc2[mi][ni], A[mi], B2[gj][p], B2[gj][p + 1]);
                }
        }
        __syncthreads();
    }

    // epilogue: g = silu(h1)*h2 -> fp16
    const int row_base = e * TE + m0 + warp_m * 64;
    const int col_base = n0 + warp_n * 32;
    #pragma unroll
    for (int mi = 0; mi < 4; ++mi)
        #pragma unroll
        for (int ni = 0; ni < 4; ++ni) {
            const int r0 = row_base + mi * 16 + (lane >> 2);
            const int col = col_base + ni * 8 + 2 * (lane & 3);
            #pragma unroll
            for (int h = 0; h < 2; ++h) {
                const float h1a = acc1[mi][ni][2 * h], h1b = acc1[mi][ni][2 * h + 1];
                const float h2a = acc2[mi][ni][2 * h], h2b = acc2[mi][ni][2 * h + 1];
                const float ga = h1a / (1.0f + __expf(-h1a)) * h2a;
                const float gb = h1b / (1.0f + __expf(-h1b)) * h2b;
                *(uint32_t*)(g_g + (size_t)(r0 + 8 * h) * HE + col) =
                    pack_h2(__float2half_rn(ga), __float2half_rn(gb));
            }
        }
}

// ---------------------------------------------------------------------------
// GEMM3: out_e = g_e @ w3_e. CTA 128x128, K=1024 staged 64 wide (16KB tiles),
// 3 buffers = 96KB, 2 CTA/SM, 16 iterations. Same proven pipeline pattern.
// ---------------------------------------------------------------------------
#define ST3 (2 * TBL)

__global__ void __launch_bounds__(256, 2) moe_mma3(float* __restrict__ out) {
    extern __shared__ __align__(128) char smem[];
    const uint32_t sb = smem_u32(smem);

    const int tid = threadIdx.x;
    const int wid = tid >> 5, lane = tid & 31;
    const int warp_m = wid >> 2, warp_n = wid & 3;
    const int e = blockIdx.z;
    const int m0 = blockIdx.y * 128;
    const int n0 = blockIdx.x * 128;

    const __half* sA = g_g   + (size_t)(e * TE + m0) * HE;
    const __half* sB = g_w3t + (size_t)e * DD * HE + (size_t)n0 * HE;

    uint32_t aRow[4], aS[4];
    #pragma unroll
    for (int mi = 0; mi < 4; ++mi) {
        int r = warp_m * 64 + mi * 16 + (lane & 15);
        aRow[mi] = r * 128;
        aS[mi] = r & 7;
    }
    const uint32_t aC = lane >> 4;
    uint32_t bRow[2], bS[2];
    #pragma unroll
    for (int gj = 0; gj < 2; ++gj) {
        int r = warp_n * 32 + gj * 16 + (lane & 7) + ((lane & 16) >> 1);
        bRow[gj] = r * 128;
        bS[gj] = r & 7;
    }
    const uint32_t bC = (lane >> 3) & 1;

    float acc[4][4][4];
    #pragma unroll
    for (int mi = 0; mi < 4; ++mi)
        #pragma unroll
        for (int ni = 0; ni < 4; ++ni)
            #pragma unroll
            for (int q = 0; q < 4; ++q) acc[mi][ni][q] = 0.f;

    auto load_stage = [&](int st, int buf) {
        const int k0 = st * 64;
        const uint32_t b = sb + buf * ST3;
        load_tile64<HE>(sA, b,       k0, tid);
        load_tile64<HE>(sB, b + TBL, k0, tid);
    };

    const int NC = HE / 64;   // 16 stages
    load_stage(0, 0); cp_commit();
    load_stage(1, 1); cp_commit();

    for (int i = 0; i < NC; ++i) {
        if (i + 2 < NC) load_stage(i + 2, (i + 2) % 3);
        cp_commit();
        cp_wait<2>();
        __syncthreads();

        const uint32_t tA = sb + (i % 3) * ST3;
        const uint32_t tB = tA + TBL;

        #pragma unroll
        for (int ks = 0; ks < 4; ++ks) {
            const uint32_t kc = ks * 2;
            uint32_t A[4][4], B[2][4];
            #pragma unroll
            for (int mi = 0; mi < 4; ++mi)
                ldsm4(A[mi], tA + aRow[mi] + (((kc + aC) ^ aS[mi]) << 4));
            #pragma unroll
            for (int gj = 0; gj < 2; ++gj)
                ldsm4(B[gj], tB + bRow[gj] + (((kc + bC) ^ bS[gj]) << 4));
            #pragma unroll
            for (int mi = 0; mi < 4; ++mi)
                #pragma unroll
                for (int ni = 0; ni < 4; ++ni) {
                    const int gj = ni >> 1, p = (ni & 1) * 2;
                    mma16816(acc[mi][ni], A[mi], B[gj][p], B[gj][p + 1]);
                }
        }
        __syncthreads();
    }

    const int row_base = e * TE + m0 + warp_m * 64;
    const int col_base = n0 + warp_n * 32;
    #pragma unroll
    for (int mi = 0; mi < 4; ++mi)
        #pragma unroll
        for (int ni = 0; ni < 4; ++ni) {
            const int r0 = row_base + mi * 16 + (lane >> 2);
            const int col = col_base + ni * 8 + 2 * (lane & 3);
            *(float2*)(out + (size_t)r0 * DD + col) =
                make_float2(acc[mi][ni][0], acc[mi][ni][1]);
            *(float2*)(out + (size_t)(r0 + 8) * DD + col) =
                make_float2(acc[mi][ni][2], acc[mi][ni][3]);
        }
}

// ---------------------------------------------------------------------------
extern "C" void kernel_launch(void* const* d_in, const int* in_sizes, int n_in,
                              void* d_out, int out_size)
{
    const float* x  = (const float*)d_in[0];
    const float* w1 = (const float*)d_in[1];
    const float* w2 = (const float*)d_in[2];
    const float* w3 = (const float*)d_in[3];
    float* out = (float*)d_out;

    cudaFuncSetAttribute(moe_mma12, cudaFuncAttributeMaxDynamicSharedMemorySize, 3 * ST12);
    cudaFuncSetAttribute(moe_mma3,  cudaFuncAttributeMaxDynamicSharedMemorySize, 3 * ST3);

    __half *xh, *w1h, *w2h, *w3t;
    cudaGetSymbolAddress((void**)&xh,  g_xh);
    cudaGetSymbolAddress((void**)&w1h, g_w1h);
    cudaGetSymbolAddress((void**)&w2h, g_w2h);
    cudaGetSymbolAddress((void**)&w3t, g_w3t);

    convert_all_kernel<<<4096, 256>>>(x, w1, w2, xh, w1h, w2h);
    {
        dim3 tb(32, 8);
        dim3 tg(HE / 32, DD / 32, EE);
        w3_transpose_half<<<tg, tb>>>(w3, w3t);
    }
    {
        dim3 g12(HE / 128, TE / 128, EE);   // 1024 CTAs
        moe_mma12<<<g12, 256, 3 * ST12>>>();
    }
    {
        dim3 g3(DD / 128, TE / 128, EE);    // 2048 CTAs
        moe_mma3<<<g3, 256, 3 * ST3>>>(out);
    }
}

// round 10
// speedup vs baseline: 5.8294x; 1.0017x over previous
#include <cuda_runtime.h>
#include <cuda_fp16.h>
#include <cstdint>

// MoE SwiGLU FFN via single-pass fp16 mma.sync.m16n8k16 (base-target PTX).
//  x  : [16384, 2048] f32,  w1/w2/w3 : [8192, 2048] f32,  out : [16384, 2048] f32
//  GEMM12: h1 = x_e @ w1_e^T, h2 = x_e @ w2_e^T, g = silu(h1)*h2  (dual-acc fused)
//  GEMM3 : out_e = g_e @ w3_e  (w3 pre-transposed to [e][d][h], K contiguous)

#define DD 2048
#define TT 16384
#define EE 8
#define HE 1024
#define TE 2048

// ---------------- static device scratch ----------------
__device__ __half g_xh [(size_t)TT * DD];
__device__ __half g_w1h[(size_t)EE * HE * DD];
__device__ __half g_w2h[(size_t)EE * HE * DD];
__device__ __half g_w3t[(size_t)EE * DD * HE];   // [e][d][h]
__device__ __half g_g  [(size_t)TT * HE];

// ---------------- base-target PTX helpers ----------------
__device__ __forceinline__ uint32_t smem_u32(const void* p) {
    return (uint32_t)__cvta_generic_to_shared(p);
}
__device__ __forceinline__ void cp16(uint32_t dst, const void* src) {
    asm volatile("cp.async.cg.shared.global [%0], [%1], 16;" :: "r"(dst), "l"(src));
}
__device__ __forceinline__ void cp_commit() {
    asm volatile("cp.async.commit_group;" ::: "memory");
}
template <int N>
__device__ __forceinline__ void cp_wait() {
    asm volatile("cp.async.wait_group %0;" :: "n"(N) : "memory");
}
__device__ __forceinline__ void ldsm4(uint32_t* r, uint32_t addr) {
    asm volatile("ldmatrix.sync.aligned.m8n8.x4.shared.b16 {%0,%1,%2,%3}, [%4];"
                 : "=r"(r[0]), "=r"(r[1]), "=r"(r[2]), "=r"(r[3]) : "r"(addr));
}
__device__ __forceinline__ void mma16816(float* c, const uint32_t* a,
                                         uint32_t b0, uint32_t b1) {
    asm volatile(
        "mma.sync.aligned.m16n8k16.row.col.f32.f16.f16.f32 "
        "{%0,%1,%2,%3}, {%4,%5,%6,%7}, {%8,%9}, {%0,%1,%2,%3};"
        : "+f"(c[0]), "+f"(c[1]), "+f"(c[2]), "+f"(c[3])
        : "r"(a[0]), "r"(a[1]), "r"(a[2]), "r"(a[3]), "r"(b0), "r"(b1));
}
__device__ __forceinline__ uint32_t pack_h2(__half a, __half b) {
    return (uint32_t)__half_as_ushort(a) | ((uint32_t)__half_as_ushort(b) << 16);
}

// ---------------------------------------------------------------------------
// preprocessing: one kernel converts x, w1, w2 fp32 -> fp16 (8 elems/iter).
// ---------------------------------------------------------------------------
#define N8X  ((int)((size_t)TT * DD / 8))
#define N8W  ((int)((size_t)EE * HE * DD / 8))

__global__ void convert_all_kernel(const float* __restrict__ x,
                                   const float* __restrict__ w1,
                                   const float* __restrict__ w2,
                                   __half* __restrict__ xh,
                                   __half* __restrict__ w1h,
                                   __half* __restrict__ w2h) {
    const int total = N8X + 2 * N8W;
    int idx = blockIdx.x * blockDim.x + threadIdx.x;
    int stride = gridDim.x * blockDim.x;
    for (int i = idx; i < total; i += stride) {
        const float* in;
        __half* dst;
        int j = i;
        if (j < N8X)            { in = x;  dst = xh; }
        else if (j < N8X + N8W) { in = w1; dst = w1h; j -= N8X; }
        else                    { in = w2; dst = w2h; j -= N8X + N8W; }
        float4 v0 = ((const float4*)in)[2 * j];
        float4 v1 = ((const float4*)in)[2 * j + 1];
        uint4 o;
        o.x = pack_h2(__float2half_rn(v0.x), __float2half_rn(v0.y));
        o.y = pack_h2(__float2half_rn(v0.z), __float2half_rn(v0.w));
        o.z = pack_h2(__float2half_rn(v1.x), __float2half_rn(v1.y));
        o.w = pack_h2(__float2half_rn(v1.z), __float2half_rn(v1.w));
        ((uint4*)dst)[j] = o;
    }
}

// w3 [e][h][d] -> w3t [e][d][h] fp16
__global__ void w3_transpose_half(const float* __restrict__ w3,
                                  __half* __restrict__ dst) {
    __shared__ float ts[32][33];
    const int e = blockIdx.z;
    const int h0 = blockIdx.x * 32, d0 = blockIdx.y * 32;
    const int tx = threadIdx.x, ty = threadIdx.y;  // 32 x 8
    const float* src = w3 + (size_t)e * HE * DD;
    #pragma unroll
    for (int r = 0; r < 32; r += 8)
        ts[ty + r][tx] = src[(size_t)(h0 + ty + r) * DD + d0 + tx];
    __syncthreads();
    __half* dh = dst + (size_t)e * DD * HE;
    #pragma unroll
    for (int r = 0; r < 32; r += 8)
        dh[(size_t)(d0 + ty + r) * HE + h0 + tx] = __float2half_rn(ts[tx][ty + r]);
}

// ---------------------------------------------------------------------------
// Shared tile machinery: 128 rows x 64 fp16 cols (128B rows, 16KB),
// swizzle c ^= r&7 — conflict-free for cp.async stores & all ldmatrix phases.
// ---------------------------------------------------------------------------
#define TBL 16384

template <int LDE>
__device__ __forceinline__ void load_tile64(const __half* __restrict__ src,
                                            uint32_t dst_base, int k0, int tid) {
    #pragma unroll
    for (int j = 0; j < 4; ++j) {
        int q = tid + 256 * j;
        int r = q >> 3, c = q & 7;
        uint32_t dst = dst_base + r * 128 + ((c ^ (r & 7)) << 4);
        cp16(dst, src + (size_t)r * LDE + k0 + c * 8);
    }
}

// ---------------------------------------------------------------------------
// GEMM12: CTA = 128 tokens x 128 hidden, dual accumulators (w1/w2 share A).
// 8 warps (2m x 4n), warp tile 64x32 per weight. K staged 64 wide, 3 buffers.
// NEW: register-fragment double buffering — ldsm for k-step ks+1 issues
// BEFORE the MMAs of step ks, hiding LDS latency under HMMA issue. Only one
// cold ldsm bubble per stage (right after the barrier) remains.
// smem: 3 x 3 x 16KB = 144KB. 1 CTA/SM, no reg cap (launch_bounds(256,1)).
// ---------------------------------------------------------------------------
#define ST12 (3 * TBL)

__global__ void __launch_bounds__(256, 1) moe_mma12() {
    extern __shared__ __align__(128) char smem[];
    const uint32_t sb = smem_u32(smem);

    const int tid = threadIdx.x;
    const int wid = tid >> 5, lane = tid & 31;
    const int warp_m = wid >> 2, warp_n = wid & 3;
    const int e = blockIdx.z;
    const int m0 = blockIdx.y * 128;
    const int n0 = blockIdx.x * 128;

    const __half* sX  = g_xh  + (size_t)(e * TE + m0) * DD;
    const __half* sW1 = g_w1h + (size_t)(e * HE + n0) * DD;
    const __half* sW2 = g_w2h + (size_t)(e * HE + n0) * DD;

    uint32_t aRow[4], aS[4];
    #pragma unroll
    for (int mi = 0; mi < 4; ++mi) {
        int r = warp_m * 64 + mi * 16 + (lane & 15);
        aRow[mi] = r * 128;
        aS[mi] = r & 7;
    }
    const uint32_t aC = lane >> 4;
    uint32_t bRow[2], bS[2];
    #pragma unroll
    for (int gj = 0; gj < 2; ++gj) {
        int r = warp_n * 32 + gj * 16 + (lane & 7) + ((lane & 16) >> 1);
        bRow[gj] = r * 128;
        bS[gj] = r & 7;
    }
    const uint32_t bC = (lane >> 3) & 1;

    float acc1[4][4][4], acc2[4][4][4];
    #pragma unroll
    for (int mi = 0; mi < 4; ++mi)
        #pragma unroll
        for (int ni = 0; ni < 4; ++ni)
            #pragma unroll
            for (int q = 0; q < 4; ++q) { acc1[mi][ni][q] = 0.f; acc2[mi][ni][q] = 0.f; }

    auto load_stage = [&](int st, int buf) {
        const int k0 = st * 64;
        const uint32_t b = sb + buf * ST12;
        load_tile64<DD>(sX,  b,           k0, tid);
        load_tile64<DD>(sW1, b + TBL,     k0, tid);
        load_tile64<DD>(sW2, b + 2 * TBL, k0, tid);
    };

    // double-buffered register fragments
    uint32_t A[2][4][4], B1[2][2][4], B2[2][2][4];

    auto ldsm_step = [&](int ks, int buf, uint32_t tX, uint32_t tW1, uint32_t tW2) {
        const uint32_t kc = (uint32_t)ks * 2;
        #pragma unroll
        for (int mi = 0; mi < 4; ++mi)
            ldsm4(A[buf][mi], tX + aRow[mi] + (((kc + aC) ^ aS[mi]) << 4));
        #pragma unroll
        for (int gj = 0; gj < 2; ++gj) {
            uint32_t c1 = (((kc + bC) ^ bS[gj]) << 4);
            ldsm4(B1[buf][gj], tW1 + bRow[gj] + c1);
            ldsm4(B2[buf][gj], tW2 + bRow[gj] + c1);
        }
    };
    auto mma_step = [&](int buf) {
        #pragma unroll
        for (int mi = 0; mi < 4; ++mi)
            #pragma unroll
            for (int ni = 0; ni < 4; ++ni) {
                const int gj = ni >> 1, p = (ni & 1) * 2;
                mma16816(acc1[mi][ni], A[buf][mi], B1[buf][gj][p], B1[buf][gj][p + 1]);
                mma16816(acc2[mi][ni], A[buf][mi], B2[buf][gj][p], B2[buf][gj][p + 1]);
            }
    };

    const int NC = DD / 64;   // 32 stages
    load_stage(0, 0); cp_commit();
    load_stage(1, 1); cp_commit();

    for (int i = 0; i < NC; ++i) {
        if (i + 2 < NC) load_stage(i + 2, (i + 2) % 3);
        cp_commit();
        cp_wait<2>();
        __syncthreads();

        const uint32_t tX  = sb + (i % 3) * ST12;
        const uint32_t tW1 = tX + TBL;
        const uint32_t tW2 = tX + 2 * TBL;

        ldsm_step(0, 0, tX, tW1, tW2);
        #pragma unroll
        for (int ks = 0; ks < 4; ++ks) {
            if (ks < 3) ldsm_step(ks + 1, (ks + 1) & 1, tX, tW1, tW2);
            mma_step(ks & 1);
        }
        __syncthreads();
    }

    // epilogue: g = silu(h1)*h2 -> fp16
    const int row_base = e * TE + m0 + warp_m * 64;
    const int col_base = n0 + warp_n * 32;
    #pragma unroll
    for (int mi = 0; mi < 4; ++mi)
        #pragma unroll
        for (int ni = 0; ni < 4; ++ni) {
            const int r0 = row_base + mi * 16 + (lane >> 2);
            const int col = col_base + ni * 8 + 2 * (lane & 3);
            #pragma unroll
            for (int h = 0; h < 2; ++h) {
                const float h1a = acc1[mi][ni][2 * h], h1b = acc1[mi][ni][2 * h + 1];
                const float h2a = acc2[mi][ni][2 * h], h2b = acc2[mi][ni][2 * h + 1];
                const float ga = h1a / (1.0f + __expf(-h1a)) * h2a;
                const float gb = h1b / (1.0f + __expf(-h1b)) * h2b;
                *(uint32_t*)(g_g + (size_t)(r0 + 8 * h) * HE + col) =
                    pack_h2(__float2half_rn(ga), __float2half_rn(gb));
            }
        }
}

// ---------------------------------------------------------------------------
// GEMM3 (unchanged from R9, which measured 173.7us / tensor 65.8%):
// out_e = g_e @ w3_e. CTA 128x128, K=1024 staged 64 wide, 3 buffers = 96KB,
// 2 CTA/SM (128-reg cap — no room for fragment double buffering here).
// ---------------------------------------------------------------------------
#define ST3 (2 * TBL)

__global__ void __launch_bounds__(256, 2) moe_mma3(float* __restrict__ out) {
    extern __shared__ __align__(128) char smem[];
    const uint32_t sb = smem_u32(smem);

    const int tid = threadIdx.x;
    const int wid = tid >> 5, lane = tid & 31;
    const int warp_m = wid >> 2, warp_n = wid & 3;
    const int e = blockIdx.z;
    const int m0 = blockIdx.y * 128;
    const int n0 = blockIdx.x * 128;

    const __half* sA = g_g   + (size_t)(e * TE + m0) * HE;
    const __half* sB = g_w3t + (size_t)e * DD * HE + (size_t)n0 * HE;

    uint32_t aRow[4], aS[4];
    #pragma unroll
    for (int mi = 0; mi < 4; ++mi) {
        int r = warp_m * 64 + mi * 16 + (lane & 15);
        aRow[mi] = r * 128;
        aS[mi] = r & 7;
    }
    const uint32_t aC = lane >> 4;
    uint32_t bRow[2], bS[2];
    #pragma unroll
    for (int gj = 0; gj < 2; ++gj) {
        int r = warp_n * 32 + gj * 16 + (lane & 7) + ((lane & 16) >> 1);
        bRow[gj] = r * 128;
        bS[gj] = r & 7;
    }
    const uint32_t bC = (lane >> 3) & 1;

    float acc[4][4][4];
    #pragma unroll
    for (int mi = 0; mi < 4; ++mi)
        #pragma unroll
        for (int ni = 0; ni < 4; ++ni)
            #pragma unroll
            for (int q = 0; q < 4; ++q) acc[mi][ni][q] = 0.f;

    auto load_stage = [&](int st, int buf) {
        const int k0 = st * 64;
        const uint32_t b = sb + buf * ST3;
        load_tile64<HE>(sA, b,       k0, tid);
        load_tile64<HE>(sB, b + TBL, k0, tid);
    };

    const int NC = HE / 64;   // 16 stages
    load_stage(0, 0); cp_commit();
    load_stage(1, 1); cp_commit();

    for (int i = 0; i < NC; ++i) {
        if (i + 2 < NC) load_stage(i + 2, (i + 2) % 3);
        cp_commit();
        cp_wait<2>();
        __syncthreads();

        const uint32_t tA = sb + (i % 3) * ST3;
        const uint32_t tB = tA + TBL;

        #pragma unroll
        for (int ks = 0; ks < 4; ++ks) {
            const uint32_t kc = ks * 2;
            uint32_t A[4][4], B[2][4];
            #pragma unroll
            for (int mi = 0; mi < 4; ++mi)
                ldsm4(A[mi], tA + aRow[mi] + (((kc + aC) ^ aS[mi]) << 4));
            #pragma unroll
            for (int gj = 0; gj < 2; ++gj)
                ldsm4(B[gj], tB + bRow[gj] + (((kc + bC) ^ bS[gj]) << 4));
            #pragma unroll
            for (int mi = 0; mi < 4; ++mi)
                #pragma unroll
                for (int ni = 0; ni < 4; ++ni) {
                    const int gj = ni >> 1, p = (ni & 1) * 2;
                    mma16816(acc[mi][ni], A[mi], B[gj][p], B[gj][p + 1]);
                }
        }
        __syncthreads();
    }

    const int row_base = e * TE + m0 + warp_m * 64;
    const int col_base = n0 + warp_n * 32;
    #pragma unroll
    for (int mi = 0; mi < 4; ++mi)
        #pragma unroll
        for (int ni = 0; ni < 4; ++ni) {
            const int r0 = row_base + mi * 16 + (lane >> 2);
            const int col = col_base + ni * 8 + 2 * (lane & 3);
            *(float2*)(out + (size_t)r0 * DD + col) =
                make_float2(acc[mi][ni][0], acc[mi][ni][1]);
            *(float2*)(out + (size_t)(r0 + 8) * DD + col) =
                make_float2(acc[mi][ni][2], acc[mi][ni][3]);
        }
}

// ---------------------------------------------------------------------------
extern "C" void kernel_launch(void* const* d_in, const int* in_sizes, int n_in,
                              void* d_out, int out_size)
{
    const float* x  = (const float*)d_in[0];
    const float* w1 = (const float*)d_in[1];
    const float* w2 = (const float*)d_in[2];
    const float* w3 = (const float*)d_in[3];
    float* out = (float*)d_out;

    cudaFuncSetAttribute(moe_mma12, cudaFuncAttributeMaxDynamicSharedMemorySize, 3 * ST12);
    cudaFuncSetAttribute(moe_mma3,  cudaFuncAttributeMaxDynamicSharedMemorySize, 3 * ST3);

    __half *xh, *w1h, *w2h, *w3t;
    cudaGetSymbolAddress((void**)&xh,  g_xh);
    cudaGetSymbolAddress((void**)&w1h, g_w1h);
    cudaGetSymbolAddress((void**)&w2h, g_w2h);
    cudaGetSymbolAddress((void**)&w3t, g_w3t);

    convert_all_kernel<<<4096, 256>>>(x, w1, w2, xh, w1h, w2h);
    {
        dim3 tb(32, 8);
        dim3 tg(HE / 32, DD / 32, EE);
        w3_transpose_half<<<tg, tb>>>(w3, w3t);
    }
    {
        dim3 g12(HE / 128, TE / 128, EE);   // 1024 CTAs
        moe_mma12<<<g12, 256, 3 * ST12>>>();
    }
    {
        dim3 g3(DD / 128, TE / 128, EE);    // 2048 CTAs
        moe_mma3<<<g3, 256, 3 * ST3>>>(out);
    }
}